// round 4
// baseline (speedup 1.0000x reference)
#include <cuda_runtime.h>
#include <cstdint>

#define BT_TOT 192
#define NN 64
#define DM 128
#define TT 96
#define SCOLS 320   // 0-127: G=Z@(Wq Wk^T), 128-255: Vt=Z@(Wv Wth), 256-287: qh, 288-319: kh

__device__ float g_Wcat[128 * SCOLS];
__device__ float g_S1[12288 * SCOLS];

// ---------------- K0: fuse weights into g_Wcat (tiled 32x32 GEMM, K=128) ----------------
// col tiles ct: 0-3 -> Wq@Wk^T, 4-7 -> Wv@Wth, 8 -> Wq@W1[:128], 9 -> Wk@W1[128:256]
__global__ void __launch_bounds__(256) k0_fuse(
    const float* __restrict__ Wq, const float* __restrict__ Wk,
    const float* __restrict__ Wv, const float* __restrict__ W1,
    const float* __restrict__ Wth) {
    __shared__ float As[32 * 132];   // A rows (k) x K=128 (m), stride 132
    __shared__ float Bs[128 * 36];   // B: K=128 (m) x 32 cols, stride 36
    int ct = blockIdx.x;   // 0..9
    int rt = blockIdx.y;   // 0..3
    int r0 = rt * 32;
    int tid = threadIdx.x;

    const float* Asrc = (ct < 4) ? Wq : (ct < 8) ? Wv : (ct == 8) ? Wq : Wk;
    // load A tile: 32 x 128, coalesced
    #pragma unroll
    for (int it = 0; it < 4; it++) {
        int idx = tid + it * 256;
        int i = idx >> 5, c4 = (idx & 31) * 4;
        *(float4*)(As + i * 132 + c4) = *(const float4*)(Asrc + (r0 + i) * 128 + c4);
    }
    // load B tile
    if (ct < 4) {
        // Bs[m][c] = Wk[(ct*32+c)*128 + m]  (read coalesced by m, store transposed)
        #pragma unroll
        for (int it = 0; it < 4; it++) {
            int idx = tid + it * 256;
            int c = idx >> 5, m4 = (idx & 31) * 4;
            float4 v = *(const float4*)(Wk + (ct * 32 + c) * 128 + m4);
            Bs[(m4 + 0) * 36 + c] = v.x;
            Bs[(m4 + 1) * 36 + c] = v.y;
            Bs[(m4 + 2) * 36 + c] = v.z;
            Bs[(m4 + 3) * 36 + c] = v.w;
        }
    } else if (ct < 8) {
        // Bs[m][c] = Wth[m*128 + (ct-4)*32 + c]
        #pragma unroll
        for (int it = 0; it < 4; it++) {
            int idx = tid + it * 256;
            int m = idx >> 3, c4 = (idx & 7) * 4;
            float4 v = *(const float4*)(Wth + m * 128 + (ct - 4) * 32 + c4);
            *(float4*)(Bs + m * 36 + c4) = v;
        }
    } else {
        int off = (ct == 9) ? 128 : 0;
        #pragma unroll
        for (int it = 0; it < 4; it++) {
            int idx = tid + it * 256;
            int m = idx >> 3, c4 = (idx & 7) * 4;
            float4 v = *(const float4*)(W1 + (off + m) * 32 + c4);
            *(float4*)(Bs + m * 36 + c4) = v;
        }
    }
    __syncthreads();

    int tx = tid & 15, ty = tid >> 4;   // 2 cols, 2 rows per thread
    float a00 = 0.f, a01 = 0.f, a10 = 0.f, a11 = 0.f;
    #pragma unroll 8
    for (int m = 0; m < 128; m++) {
        float x0 = As[(ty * 2 + 0) * 132 + m];
        float x1 = As[(ty * 2 + 1) * 132 + m];
        float y0 = Bs[m * 36 + tx * 2 + 0];
        float y1 = Bs[m * 36 + tx * 2 + 1];
        a00 = fmaf(x0, y0, a00); a01 = fmaf(x0, y1, a01);
        a10 = fmaf(x1, y0, a10); a11 = fmaf(x1, y1, a11);
    }
    int orow = r0 + ty * 2, ocol = ct * 32 + tx * 2;
    g_Wcat[(orow + 0) * SCOLS + ocol + 0] = a00;
    g_Wcat[(orow + 0) * SCOLS + ocol + 1] = a01;
    g_Wcat[(orow + 1) * SCOLS + ocol + 0] = a10;
    g_Wcat[(orow + 1) * SCOLS + ocol + 1] = a11;
}

// ---------------- K1: S1[12288,320] = Z[12288,128] @ Wcat[128,320] ----------------
__global__ void __launch_bounds__(256) k1_gemm(const float* __restrict__ x) {
    __shared__ float As[128 * 32];
    __shared__ float Bs[32 * 128];
    int m0 = blockIdx.x * 128;
    int n0 = blockIdx.y * 128;
    int tid = threadIdx.x;
    int tx = tid & 15, ty = tid >> 4;
    float acc[8][8];
    #pragma unroll
    for (int u = 0; u < 8; u++)
        #pragma unroll
        for (int v = 0; v < 8; v++) acc[u][v] = 0.f;

    for (int kk = 0; kk < 128; kk += 32) {
        #pragma unroll
        for (int it = 0; it < 4; it++) {
            int idx = tid + it * 256;
            int i = idx >> 3, c4 = (idx & 7) * 4;
            int r = m0 + i;
            int bt = r >> 6, n = r & 63;
            int b = bt / 96, t = bt - b * 96;
            float4 v = *(const float4*)(x + (size_t)(((b * 64 + n) * 96 + t)) * 128 + kk + c4);
            *(float4*)(As + i * 32 + c4) = v;
        }
        #pragma unroll
        for (int it = 0; it < 4; it++) {
            int idx = tid + it * 256;
            int kr = idx >> 5, c4 = (idx & 31) * 4;
            int col = n0 + c4;
            float4 v = make_float4(0.f, 0.f, 0.f, 0.f);
            if (col < SCOLS) v = *(const float4*)(g_Wcat + (kk + kr) * SCOLS + col);
            *(float4*)(Bs + kr * 128 + c4) = v;
        }
        __syncthreads();
        #pragma unroll
        for (int k = 0; k < 32; k++) {
            float a[8], bb[8];
            #pragma unroll
            for (int u = 0; u < 8; u++) a[u] = As[(ty * 8 + u) * 32 + k];
            float4 b0 = *(float4*)(Bs + k * 128 + tx * 8);
            float4 b1 = *(float4*)(Bs + k * 128 + tx * 8 + 4);
            bb[0] = b0.x; bb[1] = b0.y; bb[2] = b0.z; bb[3] = b0.w;
            bb[4] = b1.x; bb[5] = b1.y; bb[6] = b1.z; bb[7] = b1.w;
            #pragma unroll
            for (int u = 0; u < 8; u++)
                #pragma unroll
                for (int v = 0; v < 8; v++) acc[u][v] = fmaf(a[u], bb[v], acc[u][v]);
        }
        __syncthreads();
    }
    if (n0 + tx * 8 < SCOLS) {
        #pragma unroll
        for (int u = 0; u < 8; u++) {
            int r = m0 + ty * 8 + u;
            *(float4*)(g_S1 + (size_t)r * SCOLS + n0 + tx * 8) =
                make_float4(acc[u][0], acc[u][1], acc[u][2], acc[u][3]);
            *(float4*)(g_S1 + (size_t)r * SCOLS + n0 + tx * 8 + 4) =
                make_float4(acc[u][4], acc[u][5], acc[u][6], acc[u][7]);
        }
    }
}

// ---------------- K2: fused attention, 2 blocks per bt (i-halves) ----------------
__global__ void __launch_bounds__(256, 3) k2_attn(
    const float* __restrict__ x, const float* __restrict__ edge,
    const float* __restrict__ prior, const unsigned char* __restrict__ maskp,
    const float* __restrict__ W1, const float* __restrict__ b1,
    const float* __restrict__ W2, const float* __restrict__ b2,
    const float* __restrict__ Wfuse, const float* __restrict__ lng,
    const float* __restrict__ lnb, const float* __restrict__ pw,
    const float* __restrict__ prw, float* __restrict__ out) {
    extern __shared__ float sm[];
    float* Zs   = sm;               // 64*132  (all 64 rows of Z)
    float* Gs   = Zs + 64 * 132;    // 32*132  (own half of G; reused as h)
    float* qhs  = Gs + 32 * 132;    // 32*32
    float* khs  = qhs + 32 * 32;    // 64*36   (overlay: alphaT[j][i_local], 64*36)
    float* Ls   = khs + 64 * 36;    // 32*64
    float* W1eT = Ls + 32 * 64;     // 32*4
    float* b1s  = W1eT + 128;       // 32
    float* W2s  = b1s + 32;         // 32
    float* lngs = W2s + 32;         // 128
    float* lnbs = lngs + 128;       // 128
    float* Wfs  = lnbs + 128;       // 8
    float* msk  = Wfs + 8;          // 64
    float* alphaT = khs;

    int bt = blockIdx.x;
    int ihalf = blockIdx.y;          // 0 or 1: rows ihalf*32 .. +31
    int b = bt / 96, t = bt - b * 96;
    int tid = threadIdx.x;
    int warp = tid >> 5, lane = tid & 31;

    // ---- Phase A: loads ----
    const float* xbase = x + (size_t)((b * 64) * 96 + t) * 128;
    const float* s1 = g_S1 + (size_t)(bt * 64) * SCOLS;
    #pragma unroll
    for (int it = 0; it < 8; it++) {
        int idx = tid + it * 256;
        int i = idx >> 5, c4 = (idx & 31) * 4;
        *(float4*)(Zs + i * 132 + c4) = *(const float4*)(xbase + (size_t)i * 96 * 128 + c4);
    }
    #pragma unroll
    for (int it = 0; it < 4; it++) {
        int idx = tid + it * 256;
        int i = idx >> 5, c4 = (idx & 31) * 4;
        *(float4*)(Gs + i * 132 + c4) = *(const float4*)(s1 + (size_t)(ihalf * 32 + i) * SCOLS + c4);
    }
    {
        int idx = tid;
        int i = idx >> 3, c4 = (idx & 7) * 4;
        *(float4*)(qhs + i * 32 + c4) = *(const float4*)(s1 + (size_t)(ihalf * 32 + i) * SCOLS + 256 + c4);
    }
    #pragma unroll
    for (int it = 0; it < 2; it++) {
        int idx = tid + it * 256;
        int i = idx >> 3, c4 = (idx & 7) * 4;
        *(float4*)(khs + i * 36 + c4) = *(const float4*)(s1 + (size_t)i * SCOLS + 288 + c4);
    }
    if (tid < 128) {
        int tt = tid >> 2, c = tid & 3;
        W1eT[tt * 4 + c] = W1[(256 + c) * 32 + tt];
        lngs[tid] = lng[tid];
        lnbs[tid] = lnb[tid];
    }
    if (tid < 32) { b1s[tid] = b1[tid]; W2s[tid] = W2[tid]; }
    if (tid < 5) Wfs[tid] = Wfuse[tid];
    if (tid < 64) msk[tid] = (float)maskp[b * 64 + tid];
    __syncthreads();

    float pwv = pw[0], prwv = prw[0], b2v = b2[0];

    // ---- Phase B: logits for 32 rows x 64 cols ----
    const float* ebase = edge + (size_t)bt * 4096 * 4 + (size_t)ihalf * 32 * 64 * 4;
    const float* pbase = prior + (size_t)bt * 4096 * 5 + (size_t)ihalf * 32 * 64 * 5;
    int ib = tid >> 6;      // 0..3
    int j = tid & 63;
    #pragma unroll 1
    for (int ii = 0; ii < 8; ii++) {
        int i = ib + ii * 4;           // local row 0..31
        float cx = 0.f, cy = 0.f, cz = 0.f, cw = 0.f;
        #pragma unroll
        for (int d4 = 0; d4 < 128; d4 += 4) {
            float4 g = *(float4*)(Gs + i * 132 + d4);
            float4 z = *(float4*)(Zs + j * 132 + d4);
            cx = fmaf(g.x, z.x, cx); cy = fmaf(g.y, z.y, cy);
            cz = fmaf(g.z, z.z, cz); cw = fmaf(g.w, z.w, cw);
        }
        float content = (cx + cy + cz + cw) * 0.08838834764831845f;
        float4 e = *(const float4*)(ebase + (size_t)(i * 64 + j) * 4);
        float phys = 0.f;
        #pragma unroll
        for (int t4 = 0; t4 < 32; t4 += 4) {
            float4 khv = *(float4*)(khs + j * 36 + t4);
            float4 qhv = *(float4*)(qhs + i * 32 + t4);
            float4 bv  = *(float4*)(b1s + t4);
            float4 wv  = *(float4*)(W2s + t4);
            float4 w0 = *(float4*)(W1eT + (t4 + 0) * 4);
            float4 w1 = *(float4*)(W1eT + (t4 + 1) * 4);
            float4 w2 = *(float4*)(W1eT + (t4 + 2) * 4);
            float4 w3 = *(float4*)(W1eT + (t4 + 3) * 4);
            float h;
            h = qhv.x + khv.x + bv.x + e.x*w0.x + e.y*w0.y + e.z*w0.z + e.w*w0.w;
            phys = fmaf(fmaxf(h, 0.f), wv.x, phys);
            h = qhv.y + khv.y + bv.y + e.x*w1.x + e.y*w1.y + e.z*w1.z + e.w*w1.w;
            phys = fmaf(fmaxf(h, 0.f), wv.y, phys);
            h = qhv.z + khv.z + bv.z + e.x*w2.x + e.y*w2.y + e.z*w2.z + e.w*w2.w;
            phys = fmaf(fmaxf(h, 0.f), wv.z, phys);
            h = qhv.w + khv.w + bv.w + e.x*w3.x + e.y*w3.y + e.z*w3.z + e.w*w3.w;
            phys = fmaf(fmaxf(h, 0.f), wv.w, phys);
        }
        phys += b2v;
        const float* ap = pbase + (size_t)(i * 64 + j) * 5;
        float Ap = ap[0]*Wfs[0] + ap[1]*Wfs[1] + ap[2]*Wfs[2] + ap[3]*Wfs[3] + ap[4]*Wfs[4];
        Ap = fmaxf(Ap, 0.f);
        float L = content + pwv * phys + prwv * logf(Ap + 1e-6f);
        if (msk[ihalf * 32 + i] != 0.f || msk[j] != 0.f) L = -1e9f;
        Ls[i * 64 + j] = L;
    }
    __syncthreads();

    // ---- Phase C: softmax per row (32 rows), write transposed alpha over khs ----
    #pragma unroll 1
    for (int rr = 0; rr < 4; rr++) {
        int r = warp + rr * 8;       // local row
        float v0 = Ls[r * 64 + lane], v1 = Ls[r * 64 + lane + 32];
        float m = fmaxf(v0, v1);
        #pragma unroll
        for (int o = 16; o; o >>= 1) m = fmaxf(m, __shfl_xor_sync(0xffffffffu, m, o));
        float e0 = expf(v0 - m), e1 = expf(v1 - m);
        float s = e0 + e1;
        #pragma unroll
        for (int o = 16; o; o >>= 1) s += __shfl_xor_sync(0xffffffffu, s, o);
        float inv = 1.f / s;
        alphaT[lane * 36 + r] = e0 * inv;
        alphaT[(lane + 32) * 36 + r] = e1 * inv;
    }
    __syncthreads();

    // ---- Phase D: h = Z + alpha @ Vt (V rows streamed from L2) ----
    int di = tid & 127, grp = tid >> 7;
    const float* vbase = g_S1 + (size_t)(bt * 64) * SCOLS + 128 + di;
    #pragma unroll 1
    for (int it = 0; it < 2; it++) {
        int i0 = grp * 16 + it * 8;    // local row base
        float acc[8];
        #pragma unroll
        for (int u = 0; u < 8; u++) acc[u] = Zs[(ihalf * 32 + i0 + u) * 132 + di];
        #pragma unroll 8
        for (int jj = 0; jj < 64; jj++) {
            float vv = __ldg(vbase + (size_t)jj * SCOLS);
            float4 a0 = *(float4*)(alphaT + jj * 36 + i0);
            float4 a1 = *(float4*)(alphaT + jj * 36 + i0 + 4);
            acc[0] = fmaf(a0.x, vv, acc[0]); acc[1] = fmaf(a0.y, vv, acc[1]);
            acc[2] = fmaf(a0.z, vv, acc[2]); acc[3] = fmaf(a0.w, vv, acc[3]);
            acc[4] = fmaf(a1.x, vv, acc[4]); acc[5] = fmaf(a1.y, vv, acc[5]);
            acc[6] = fmaf(a1.z, vv, acc[6]); acc[7] = fmaf(a1.w, vv, acc[7]);
        }
        #pragma unroll
        for (int u = 0; u < 8; u++) Gs[(i0 + u) * 132 + di] = acc[u];
    }
    __syncthreads();

    // ---- Phase E: LayerNorm + masked, transposed store (32 rows) ----
    float* outb = out + (size_t)((b * 64) * 96 + t) * 128;
    #pragma unroll 1
    for (int rr = 0; rr < 4; rr++) {
        int r = warp + rr * 8;         // local row
        float v[4];
        #pragma unroll
        for (int u = 0; u < 4; u++) v[u] = Gs[r * 132 + lane + 32 * u];
        float s = v[0] + v[1] + v[2] + v[3];
        #pragma unroll
        for (int o = 16; o; o >>= 1) s += __shfl_xor_sync(0xffffffffu, s, o);
        float mu = s * (1.f / 128.f);
        float q = 0.f;
        #pragma unroll
        for (int u = 0; u < 4; u++) { float d = v[u] - mu; q = fmaf(d, d, q); }
        #pragma unroll
        for (int o = 16; o; o >>= 1) q += __shfl_xor_sync(0xffffffffu, q, o);
        float inv = rsqrtf(q * (1.f / 128.f) + 1e-5f);
        int rg = ihalf * 32 + r;
        float keep = (msk[rg] != 0.f) ? 0.f : 1.f;
        float* op = outb + (size_t)rg * 96 * 128;
        #pragma unroll
        for (int u = 0; u < 4; u++) {
            int d = lane + 32 * u;
            op[d] = ((v[u] - mu) * inv * lngs[d] + lnbs[d]) * keep;
        }
    }
}

extern "C" void kernel_launch(void* const* d_in, const int* in_sizes, int n_in,
                              void* d_out, int out_size) {
    const float* x     = (const float*)d_in[0];
    const float* edge  = (const float*)d_in[1];
    const float* prior = (const float*)d_in[2];
    const unsigned char* maskp = (const unsigned char*)d_in[3];
    const float* Wq    = (const float*)d_in[4];
    const float* Wk    = (const float*)d_in[5];
    const float* Wv    = (const float*)d_in[6];
    const float* W1    = (const float*)d_in[7];
    const float* b1    = (const float*)d_in[8];
    const float* W2    = (const float*)d_in[9];
    const float* b2    = (const float*)d_in[10];
    const float* Wfuse = (const float*)d_in[11];
    const float* Wth   = (const float*)d_in[12];
    const float* lng   = (const float*)d_in[13];
    const float* lnb   = (const float*)d_in[14];
    const float* pw    = (const float*)d_in[15];
    const float* prw   = (const float*)d_in[16];
    float* out = (float*)d_out;

    const int smem2 = (64*132 + 32*132 + 32*32 + 64*36 + 32*64
                       + 128 + 32 + 32 + 128 + 128 + 8 + 64) * sizeof(float);
    cudaFuncSetAttribute(k2_attn, cudaFuncAttributeMaxDynamicSharedMemorySize, smem2);

    k0_fuse<<<dim3(10, 4), 256>>>(Wq, Wk, Wv, W1, Wth);
    k1_gemm<<<dim3(96, 3), 256>>>(x);
    k2_attn<<<dim3(192, 2), 256, smem2>>>(x, edge, prior, maskp, W1, b1, W2, b2,
                                          Wfuse, lng, lnb, pw, prw, out);
}

// round 7
// speedup vs baseline: 1.1465x; 1.1465x over previous
#include <cuda_runtime.h>
#include <cstdint>

#define BT_TOT 192
#define NN 64
#define DM 128
#define TT 96
#define SCOLS 320   // 0-127: G=Z@(Wq Wk^T), 128-255: Vt=Z@(Wv Wth), 256-287: qh, 288-319: kh

__device__ float g_Wcat[128 * SCOLS];
__device__ float g_S1[12288 * SCOLS];

// ---------------- K0: fuse weights into g_Wcat (tiled 32x32 GEMM, K=128) ----------------
__global__ void __launch_bounds__(256) k0_fuse(
    const float* __restrict__ Wq, const float* __restrict__ Wk,
    const float* __restrict__ Wv, const float* __restrict__ W1,
    const float* __restrict__ Wth) {
    __shared__ float As[32 * 132];
    __shared__ float Bs[128 * 36];
    int ct = blockIdx.x;   // 0..9
    int rt = blockIdx.y;   // 0..3
    int r0 = rt * 32;
    int tid = threadIdx.x;

    const float* Asrc = (ct < 4) ? Wq : (ct < 8) ? Wv : (ct == 8) ? Wq : Wk;
    #pragma unroll
    for (int it = 0; it < 4; it++) {
        int idx = tid + it * 256;
        int i = idx >> 5, c4 = (idx & 31) * 4;
        *(float4*)(As + i * 132 + c4) = *(const float4*)(Asrc + (r0 + i) * 128 + c4);
    }
    if (ct < 4) {
        #pragma unroll
        for (int it = 0; it < 4; it++) {
            int idx = tid + it * 256;
            int c = idx >> 5, m4 = (idx & 31) * 4;
            float4 v = *(const float4*)(Wk + (ct * 32 + c) * 128 + m4);
            Bs[(m4 + 0) * 36 + c] = v.x;
            Bs[(m4 + 1) * 36 + c] = v.y;
            Bs[(m4 + 2) * 36 + c] = v.z;
            Bs[(m4 + 3) * 36 + c] = v.w;
        }
    } else if (ct < 8) {
        #pragma unroll
        for (int it = 0; it < 4; it++) {
            int idx = tid + it * 256;
            int m = idx >> 3, c4 = (idx & 7) * 4;
            float4 v = *(const float4*)(Wth + m * 128 + (ct - 4) * 32 + c4);
            *(float4*)(Bs + m * 36 + c4) = v;
        }
    } else {
        int off = (ct == 9) ? 128 : 0;
        #pragma unroll
        for (int it = 0; it < 4; it++) {
            int idx = tid + it * 256;
            int m = idx >> 3, c4 = (idx & 7) * 4;
            float4 v = *(const float4*)(W1 + (off + m) * 32 + c4);
            *(float4*)(Bs + m * 36 + c4) = v;
        }
    }
    __syncthreads();

    int tx = tid & 15, ty = tid >> 4;
    float a00 = 0.f, a01 = 0.f, a10 = 0.f, a11 = 0.f;
    #pragma unroll 8
    for (int m = 0; m < 128; m++) {
        float x0 = As[(ty * 2 + 0) * 132 + m];
        float x1 = As[(ty * 2 + 1) * 132 + m];
        float y0 = Bs[m * 36 + tx * 2 + 0];
        float y1 = Bs[m * 36 + tx * 2 + 1];
        a00 = fmaf(x0, y0, a00); a01 = fmaf(x0, y1, a01);
        a10 = fmaf(x1, y0, a10); a11 = fmaf(x1, y1, a11);
    }
    int orow = r0 + ty * 2, ocol = ct * 32 + tx * 2;
    g_Wcat[(orow + 0) * SCOLS + ocol + 0] = a00;
    g_Wcat[(orow + 0) * SCOLS + ocol + 1] = a01;
    g_Wcat[(orow + 1) * SCOLS + ocol + 0] = a10;
    g_Wcat[(orow + 1) * SCOLS + ocol + 1] = a11;
}

// ---------------- K1: S1 = Z @ Wcat via 3xTF32 tensor cores ----------------
__device__ __forceinline__ uint32_t f2tf(float f) {
    uint32_t u; asm("cvt.rna.tf32.f32 %0, %1;" : "=r"(u) : "f"(f)); return u;
}
__device__ __forceinline__ void mma_tf32(float* c, const uint32_t* a, const uint32_t* b) {
    asm volatile("mma.sync.aligned.m16n8k8.row.col.f32.tf32.tf32.f32 "
        "{%0,%1,%2,%3}, {%4,%5,%6,%7}, {%8,%9}, {%0,%1,%2,%3};"
        : "+f"(c[0]), "+f"(c[1]), "+f"(c[2]), "+f"(c[3])
        : "r"(a[0]), "r"(a[1]), "r"(a[2]), "r"(a[3]), "r"(b[0]), "r"(b[1]));
}

#define K1_SMEM ((128*36*2 + 32*136*2) * 4)

__global__ void __launch_bounds__(256) k1_gemm(const float* __restrict__ x) {
    extern __shared__ uint32_t smk1[];
    uint32_t* Ah = smk1;                 // 128 x 36
    uint32_t* Al = Ah + 128 * 36;
    uint32_t* Bh = Al + 128 * 36;        // 32 x 136
    uint32_t* Bl = Bh + 32 * 136;

    int m0 = blockIdx.x * 128;
    int n0 = blockIdx.y * 128;
    int tid = threadIdx.x;
    int lane = tid & 31, warp = tid >> 5;
    int g = lane >> 2, t4 = lane & 3;
    int wm = warp >> 2, wn = warp & 3;   // 2 x 4 warp grid
    int mb = wm * 64, nb = wn * 32;

    float c[4][4][4];
    #pragma unroll
    for (int im = 0; im < 4; im++)
        #pragma unroll
        for (int in_ = 0; in_ < 4; in_++)
            #pragma unroll
            for (int q = 0; q < 4; q++) c[im][in_][q] = 0.f;

    for (int kk = 0; kk < 128; kk += 32) {
        // A chunk: 128 x 32, gathered from x
        #pragma unroll
        for (int it = 0; it < 4; it++) {
            int idx = tid + it * 256;
            int i = idx >> 3, c4 = (idx & 7) * 4;
            int r = m0 + i;
            int bt = r >> 6, n = r & 63;
            int b = bt / 96, t = bt - b * 96;
            float4 v = *(const float4*)(x + (size_t)(((b * 64 + n) * 96 + t)) * 128 + kk + c4);
            float vv[4] = {v.x, v.y, v.z, v.w};
            #pragma unroll
            for (int q = 0; q < 4; q++) {
                uint32_t hi = f2tf(vv[q]);
                float lof = vv[q] - __uint_as_float(hi);
                Ah[i * 36 + c4 + q] = hi;
                Al[i * 36 + c4 + q] = f2tf(lof);
            }
        }
        // B chunk: 32 x 128 from g_Wcat
        #pragma unroll
        for (int it = 0; it < 4; it++) {
            int idx = tid + it * 256;
            int kr = idx >> 5, c4 = (idx & 31) * 4;
            int col = n0 + c4;
            float4 v = make_float4(0.f, 0.f, 0.f, 0.f);
            if (col < SCOLS) v = *(const float4*)(g_Wcat + (kk + kr) * SCOLS + col);
            float vv[4] = {v.x, v.y, v.z, v.w};
            #pragma unroll
            for (int q = 0; q < 4; q++) {
                uint32_t hi = f2tf(vv[q]);
                float lof = vv[q] - __uint_as_float(hi);
                Bh[kr * 136 + c4 + q] = hi;
                Bl[kr * 136 + c4 + q] = f2tf(lof);
            }
        }
        __syncthreads();

        #pragma unroll
        for (int ks = 0; ks < 4; ks++) {
            int k0 = ks * 8;
            uint32_t ahi[4][4], alo[4][4], bhi[4][2], blo[4][2];
            #pragma unroll
            for (int im = 0; im < 4; im++) {
                int rA = (mb + im * 16 + g) * 36 + k0 + t4;
                int rA8 = rA + 8 * 36;
                ahi[im][0] = Ah[rA];      ahi[im][1] = Ah[rA8];
                ahi[im][2] = Ah[rA + 4];  ahi[im][3] = Ah[rA8 + 4];
                alo[im][0] = Al[rA];      alo[im][1] = Al[rA8];
                alo[im][2] = Al[rA + 4];  alo[im][3] = Al[rA8 + 4];
            }
            #pragma unroll
            for (int in_ = 0; in_ < 4; in_++) {
                int colB = nb + in_ * 8 + g;
                bhi[in_][0] = Bh[(k0 + t4) * 136 + colB];
                bhi[in_][1] = Bh[(k0 + t4 + 4) * 136 + colB];
                blo[in_][0] = Bl[(k0 + t4) * 136 + colB];
                blo[in_][1] = Bl[(k0 + t4 + 4) * 136 + colB];
            }
            #pragma unroll
            for (int im = 0; im < 4; im++)
                #pragma unroll
                for (int in_ = 0; in_ < 4; in_++) {
                    mma_tf32(c[im][in_], ahi[im], bhi[in_]);
                    mma_tf32(c[im][in_], alo[im], bhi[in_]);
                    mma_tf32(c[im][in_], ahi[im], blo[in_]);
                }
        }
        __syncthreads();
    }

    #pragma unroll
    for (int im = 0; im < 4; im++)
        #pragma unroll
        for (int in_ = 0; in_ < 4; in_++) {
            int row = m0 + mb + im * 16 + g;
            int col = n0 + nb + in_ * 8 + t4 * 2;
            if (col < SCOLS) {
                *(float2*)(g_S1 + (size_t)row * SCOLS + col) = make_float2(c[im][in_][0], c[im][in_][1]);
                *(float2*)(g_S1 + (size_t)(row + 8) * SCOLS + col) = make_float2(c[im][in_][2], c[im][in_][3]);
            }
        }
}

// ---------------- K2: fused attention, 1 block per bt, 2 blocks/SM ----------------
#define K2_SMEM ((64*132 + 64*132 + 64*32 + 64*36 + 64*64 + 128 + 32 + 32 + 128 + 128 + 8 + 64) * 4)

__global__ void __launch_bounds__(256, 2) k2_attn(
    const float* __restrict__ x, const float* __restrict__ edge,
    const float* __restrict__ prior, const unsigned char* __restrict__ maskp,
    const float* __restrict__ W1, const float* __restrict__ b1,
    const float* __restrict__ W2, const float* __restrict__ b2,
    const float* __restrict__ Wfuse, const float* __restrict__ lng,
    const float* __restrict__ lnb, const float* __restrict__ pw,
    const float* __restrict__ prw, float* __restrict__ out) {
    extern __shared__ float sm[];
    float* Zs   = sm;               // 64*132
    float* Gs   = Zs + 64 * 132;    // 64*132 (reused as h)
    float* qhs  = Gs + 64 * 132;    // 64*32   } overlay: alphaT 64*68
    float* khs  = qhs + 64 * 32;    // 64*36   }
    float* Ls   = khs + 64 * 36;    // 64*64
    float* W1eT = Ls + 64 * 64;     // 32*4
    float* b1s  = W1eT + 128;       // 32
    float* W2s  = b1s + 32;         // 32
    float* lngs = W2s + 32;         // 128
    float* lnbs = lngs + 128;       // 128
    float* Wfs  = lnbs + 128;       // 8
    float* msk  = Wfs + 8;          // 64
    float* alphaT = qhs;            // 64*68

    int bt = blockIdx.x;
    int b = bt / 96, t = bt - b * 96;
    int tid = threadIdx.x;
    int warp = tid >> 5, lane = tid & 31;

    // ---- Phase A: loads ----
    const float* xbase = x + (size_t)((b * 64) * 96 + t) * 128;
    const float* s1 = g_S1 + (size_t)(bt * 64) * SCOLS;
    #pragma unroll
    for (int it = 0; it < 8; it++) {
        int idx = tid + it * 256;
        int i = idx >> 5, c4 = (idx & 31) * 4;
        *(float4*)(Zs + i * 132 + c4) = *(const float4*)(xbase + (size_t)i * 96 * 128 + c4);
        *(float4*)(Gs + i * 132 + c4) = *(const float4*)(s1 + (size_t)i * SCOLS + c4);
    }
    #pragma unroll
    for (int it = 0; it < 2; it++) {
        int idx = tid + it * 256;
        int i = idx >> 3, c4 = (idx & 7) * 4;
        *(float4*)(qhs + i * 32 + c4) = *(const float4*)(s1 + (size_t)i * SCOLS + 256 + c4);
        *(float4*)(khs + i * 36 + c4) = *(const float4*)(s1 + (size_t)i * SCOLS + 288 + c4);
    }
    if (tid < 128) {
        int tt = tid >> 2, c = tid & 3;
        W1eT[tt * 4 + c] = W1[(256 + c) * 32 + tt];
        lngs[tid] = lng[tid];
        lnbs[tid] = lnb[tid];
    }
    if (tid < 32) { b1s[tid] = b1[tid]; W2s[tid] = W2[tid]; }
    if (tid < 5) Wfs[tid] = Wfuse[tid];
    if (tid < 64) msk[tid] = (float)maskp[b * 64 + tid];
    __syncthreads();

    float pwv = pw[0], prwv = prw[0], b2v = b2[0];

    // ---- Phase B: logits, 4x4 register tile per thread ----
    int ti = tid >> 4, tj = tid & 15;
    int i0 = ti * 4, j0 = tj * 4;
    float cc[4][4];
    #pragma unroll
    for (int u = 0; u < 4; u++)
        #pragma unroll
        for (int v = 0; v < 4; v++) cc[u][v] = 0.f;
    #pragma unroll 8
    for (int d4 = 0; d4 < 128; d4 += 4) {
        float4 gv[4], zv[4];
        #pragma unroll
        for (int u = 0; u < 4; u++) gv[u] = *(float4*)(Gs + (i0 + u) * 132 + d4);
        #pragma unroll
        for (int v = 0; v < 4; v++) zv[v] = *(float4*)(Zs + (j0 + v) * 132 + d4);
        #pragma unroll
        for (int u = 0; u < 4; u++)
            #pragma unroll
            for (int v = 0; v < 4; v++) {
                float s = fmaf(gv[u].x, zv[v].x, cc[u][v]);
                s = fmaf(gv[u].y, zv[v].y, s);
                s = fmaf(gv[u].z, zv[v].z, s);
                cc[u][v] = fmaf(gv[u].w, zv[v].w, s);
            }
    }

    const float* ebase = edge + (size_t)bt * 4096 * 4;
    const float* pbase = prior + (size_t)bt * 4096 * 5;
    #pragma unroll 1
    for (int u = 0; u < 4; u++) {
        int i = i0 + u;
        float4 e0 = *(const float4*)(ebase + (size_t)(i * 64 + j0 + 0) * 4);
        float4 e1 = *(const float4*)(ebase + (size_t)(i * 64 + j0 + 1) * 4);
        float4 e2 = *(const float4*)(ebase + (size_t)(i * 64 + j0 + 2) * 4);
        float4 e3 = *(const float4*)(ebase + (size_t)(i * 64 + j0 + 3) * 4);
        float p0 = 0.f, p1 = 0.f, p2 = 0.f, p3 = 0.f;
        #pragma unroll
        for (int t4 = 0; t4 < 32; t4 += 4) {
            float4 qhv = *(float4*)(qhs + i * 32 + t4);
            float4 bv  = *(float4*)(b1s + t4);
            float4 wv  = *(float4*)(W2s + t4);
            float4 k0v = *(float4*)(khs + (j0 + 0) * 36 + t4);
            float4 k1v = *(float4*)(khs + (j0 + 1) * 36 + t4);
            float4 k2v = *(float4*)(khs + (j0 + 2) * 36 + t4);
            float4 k3v = *(float4*)(khs + (j0 + 3) * 36 + t4);
            float4 w0 = *(float4*)(W1eT + (t4 + 0) * 4);
            float4 w1 = *(float4*)(W1eT + (t4 + 1) * 4);
            float4 w2 = *(float4*)(W1eT + (t4 + 2) * 4);
            float4 w3 = *(float4*)(W1eT + (t4 + 3) * 4);
            float base, h;
            // hidden t4+0
            base = qhv.x + bv.x;
            h = base + k0v.x + e0.x*w0.x + e0.y*w0.y + e0.z*w0.z + e0.w*w0.w; p0 = fmaf(fmaxf(h,0.f), wv.x, p0);
            h = base + k1v.x + e1.x*w0.x + e1.y*w0.y + e1.z*w0.z + e1.w*w0.w; p1 = fmaf(fmaxf(h,0.f), wv.x, p1);
            h = base + k2v.x + e2.x*w0.x + e2.y*w0.y + e2.z*w0.z + e2.w*w0.w; p2 = fmaf(fmaxf(h,0.f), wv.x, p2);
            h = base + k3v.x + e3.x*w0.x + e3.y*w0.y + e3.z*w0.z + e3.w*w0.w; p3 = fmaf(fmaxf(h,0.f), wv.x, p3);
            // hidden t4+1
            base = qhv.y + bv.y;
            h = base + k0v.y + e0.x*w1.x + e0.y*w1.y + e0.z*w1.z + e0.w*w1.w; p0 = fmaf(fmaxf(h,0.f), wv.y, p0);
            h = base + k1v.y + e1.x*w1.x + e1.y*w1.y + e1.z*w1.z + e1.w*w1.w; p1 = fmaf(fmaxf(h,0.f), wv.y, p1);
            h = base + k2v.y + e2.x*w1.x + e2.y*w1.y + e2.z*w1.z + e2.w*w1.w; p2 = fmaf(fmaxf(h,0.f), wv.y, p2);
            h = base + k3v.y + e3.x*w1.x + e3.y*w1.y + e3.z*w1.z + e3.w*w1.w; p3 = fmaf(fmaxf(h,0.f), wv.y, p3);
            // hidden t4+2
            base = qhv.z + bv.z;
            h = base + k0v.z + e0.x*w2.x + e0.y*w2.y + e0.z*w2.z + e0.w*w2.w; p0 = fmaf(fmaxf(h,0.f), wv.z, p0);
            h = base + k1v.z + e1.x*w2.x + e1.y*w2.y + e1.z*w2.z + e1.w*w2.w; p1 = fmaf(fmaxf(h,0.f), wv.z, p1);
            h = base + k2v.z + e2.x*w2.x + e2.y*w2.y + e2.z*w2.z + e2.w*w2.w; p2 = fmaf(fmaxf(h,0.f), wv.z, p2);
            h = base + k3v.z + e3.x*w2.x + e3.y*w2.y + e3.z*w2.z + e3.w*w2.w; p3 = fmaf(fmaxf(h,0.f), wv.z, p3);
            // hidden t4+3
            base = qhv.w + bv.w;
            h = base + k0v.w + e0.x*w3.x + e0.y*w3.y + e0.z*w3.z + e0.w*w3.w; p0 = fmaf(fmaxf(h,0.f), wv.w, p0);
            h = base + k1v.w + e1.x*w3.x + e1.y*w3.y + e1.z*w3.z + e1.w*w3.w; p1 = fmaf(fmaxf(h,0.f), wv.w, p1);
            h = base + k2v.w + e2.x*w3.x + e2.y*w3.y + e2.z*w3.z + e2.w*w3.w; p2 = fmaf(fmaxf(h,0.f), wv.w, p2);
            h = base + k3v.w + e3.x*w3.x + e3.y*w3.y + e3.z*w3.z + e3.w*w3.w; p3 = fmaf(fmaxf(h,0.f), wv.w, p3);
        }
        float phys[4] = {p0, p1, p2, p3};
        float Lv[4];
        #pragma unroll
        for (int v = 0; v < 4; v++) {
            const float* ap = pbase + (size_t)(i * 64 + j0 + v) * 5;
            float Ap = ap[0]*Wfs[0] + ap[1]*Wfs[1] + ap[2]*Wfs[2] + ap[3]*Wfs[3] + ap[4]*Wfs[4];
            Ap = fmaxf(Ap, 0.f);
            float L = cc[u][v] * 0.08838834764831845f + pwv * (phys[v] + b2v)
                      + prwv * __logf(Ap + 1e-6f);
            if (msk[i] != 0.f || msk[j0 + v] != 0.f) L = -1e9f;
            Lv[v] = L;
        }
        *(float4*)(Ls + i * 64 + j0) = make_float4(Lv[0], Lv[1], Lv[2], Lv[3]);
    }
    __syncthreads();

    // ---- Phase C: softmax per row, write transposed alpha (overlays qhs/khs) ----
    #pragma unroll 1
    for (int rr = 0; rr < 8; rr++) {
        int r = warp + rr * 8;
        float v0 = Ls[r * 64 + lane], v1 = Ls[r * 64 + lane + 32];
        float m = fmaxf(v0, v1);
        #pragma unroll
        for (int o = 16; o; o >>= 1) m = fmaxf(m, __shfl_xor_sync(0xffffffffu, m, o));
        float e0 = __expf(v0 - m), e1 = __expf(v1 - m);
        float s = e0 + e1;
        #pragma unroll
        for (int o = 16; o; o >>= 1) s += __shfl_xor_sync(0xffffffffu, s, o);
        float inv = 1.f / s;
        alphaT[lane * 68 + r] = e0 * inv;
        alphaT[(lane + 32) * 68 + r] = e1 * inv;
    }
    __syncthreads();

    // ---- Phase D: h = Z + alpha @ Vt (V streamed from L2) ----
    int di = tid & 127, grp = tid >> 7;
    const float* vrow = g_S1 + (size_t)(bt * 64) * SCOLS + 128 + di;
    #pragma unroll 1
    for (int it = 0; it < 2; it++) {
        int r0 = grp * 32 + it * 16;
        float acc[16];
        #pragma unroll
        for (int u = 0; u < 16; u++) acc[u] = Zs[(r0 + u) * 132 + di];
        #pragma unroll 4
        for (int jj = 0; jj < 64; jj++) {
            float vv = __ldg(vrow + (size_t)jj * SCOLS);
            float4 a0 = *(float4*)(alphaT + jj * 68 + r0);
            float4 a1 = *(float4*)(alphaT + jj * 68 + r0 + 4);
            float4 a2 = *(float4*)(alphaT + jj * 68 + r0 + 8);
            float4 a3 = *(float4*)(alphaT + jj * 68 + r0 + 12);
            acc[0]  = fmaf(a0.x, vv, acc[0]);  acc[1]  = fmaf(a0.y, vv, acc[1]);
            acc[2]  = fmaf(a0.z, vv, acc[2]);  acc[3]  = fmaf(a0.w, vv, acc[3]);
            acc[4]  = fmaf(a1.x, vv, acc[4]);  acc[5]  = fmaf(a1.y, vv, acc[5]);
            acc[6]  = fmaf(a1.z, vv, acc[6]);  acc[7]  = fmaf(a1.w, vv, acc[7]);
            acc[8]  = fmaf(a2.x, vv, acc[8]);  acc[9]  = fmaf(a2.y, vv, acc[9]);
            acc[10] = fmaf(a2.z, vv, acc[10]); acc[11] = fmaf(a2.w, vv, acc[11]);
            acc[12] = fmaf(a3.x, vv, acc[12]); acc[13] = fmaf(a3.y, vv, acc[13]);
            acc[14] = fmaf(a3.z, vv, acc[14]); acc[15] = fmaf(a3.w, vv, acc[15]);
        }
        #pragma unroll
        for (int u = 0; u < 16; u++) Gs[(r0 + u) * 132 + di] = acc[u];
    }
    __syncthreads();

    // ---- Phase E: LayerNorm + masked, transposed store ----
    float* outb = out + (size_t)((b * 64) * 96 + t) * 128;
    #pragma unroll 1
    for (int rr = 0; rr < 8; rr++) {
        int r = warp + rr * 8;
        float v[4];
        #pragma unroll
        for (int u = 0; u < 4; u++) v[u] = Gs[r * 132 + lane + 32 * u];
        float s = v[0] + v[1] + v[2] + v[3];
        #pragma unroll
        for (int o = 16; o; o >>= 1) s += __shfl_xor_sync(0xffffffffu, s, o);
        float mu = s * (1.f / 128.f);
        float q = 0.f;
        #pragma unroll
        for (int u = 0; u < 4; u++) { float d = v[u] - mu; q = fmaf(d, d, q); }
        #pragma unroll
        for (int o = 16; o; o >>= 1) q += __shfl_xor_sync(0xffffffffu, q, o);
        float inv = rsqrtf(q * (1.f / 128.f) + 1e-5f);
        float keep = (msk[r] != 0.f) ? 0.f : 1.f;
        float* op = outb + (size_t)r * 96 * 128;
        #pragma unroll
        for (int u = 0; u < 4; u++) {
            int d = lane + 32 * u;
            op[d] = ((v[u] - mu) * inv * lngs[d] + lnbs[d]) * keep;
        }
    }
}

extern "C" void kernel_launch(void* const* d_in, const int* in_sizes, int n_in,
                              void* d_out, int out_size) {
    const float* x     = (const float*)d_in[0];
    const float* edge  = (const float*)d_in[1];
    const float* prior = (const float*)d_in[2];
    const unsigned char* maskp = (const unsigned char*)d_in[3];
    const float* Wq    = (const float*)d_in[4];
    const float* Wk    = (const float*)d_in[5];
    const float* Wv    = (const float*)d_in[6];
    const float* W1    = (const float*)d_in[7];
    const float* b1    = (const float*)d_in[8];
    const float* W2    = (const float*)d_in[9];
    const float* b2    = (const float*)d_in[10];
    const float* Wfuse = (const float*)d_in[11];
    const float* Wth   = (const float*)d_in[12];
    const float* lng   = (const float*)d_in[13];
    const float* lnb   = (const float*)d_in[14];
    const float* pw    = (const float*)d_in[15];
    const float* prw   = (const float*)d_in[16];
    float* out = (float*)d_out;

    static int inited = 0;
    if (!inited) {
        cudaFuncSetAttribute(k1_gemm, cudaFuncAttributeMaxDynamicSharedMemorySize, K1_SMEM);
        cudaFuncSetAttribute(k2_attn, cudaFuncAttributeMaxDynamicSharedMemorySize, K2_SMEM);
        inited = 1;
    }

    k0_fuse<<<dim3(10, 4), 256>>>(Wq, Wk, Wv, W1, Wth);
    k1_gemm<<<dim3(96, 3), 256, K1_SMEM>>>(x);
    k2_attn<<<192, 256, K2_SMEM>>>(x, edge, prior, maskp, W1, b1, W2, b2,
                                   Wfuse, lng, lnb, pw, prw, out);
}

// round 8
// speedup vs baseline: 1.1939x; 1.0413x over previous
#include <cuda_runtime.h>
#include <cstdint>

#define BT_TOT 192
#define NN 64
#define DM 128
#define TT 96
#define SCOLS 320   // 0-127: G=Z@(Wq Wk^T), 128-255: Vt=Z@(Wv Wth), 256-287: qh, 288-319: kh

__device__ float g_Wcat[128 * SCOLS];
__device__ float g_S1[12288 * SCOLS];

typedef unsigned long long u64;
__device__ __forceinline__ u64 pk2(float lo, float hi) {
    u64 r; asm("mov.b64 %0,{%1,%2};" : "=l"(r) : "f"(lo), "f"(hi)); return r;
}
__device__ __forceinline__ float2 up2(u64 v) {
    float2 f; asm("mov.b64 {%0,%1},%2;" : "=f"(f.x), "=f"(f.y) : "l"(v)); return f;
}
__device__ __forceinline__ u64 fma2_(u64 a, u64 b, u64 c) {
    u64 d; asm("fma.rn.f32x2 %0,%1,%2,%3;" : "=l"(d) : "l"(a), "l"(b), "l"(c)); return d;
}
__device__ __forceinline__ u64 add2_(u64 a, u64 b) {
    u64 d; asm("add.rn.f32x2 %0,%1,%2;" : "=l"(d) : "l"(a), "l"(b)); return d;
}

// ---------------- K0: fuse weights into g_Wcat (32x32 tiles, f32x2 + float4 LDS) ----------------
__global__ void __launch_bounds__(256) k0_fuse(
    const float* __restrict__ Wq, const float* __restrict__ Wk,
    const float* __restrict__ Wv, const float* __restrict__ W1,
    const float* __restrict__ Wth) {
    __shared__ float As[32 * 132];   // [row][m]
    __shared__ float Bs[32 * 132];   // [col][m]  (transposed so m is contiguous)
    int ct = blockIdx.x;   // 0..9
    int rt = blockIdx.y;   // 0..3
    int r0 = rt * 32;
    int tid = threadIdx.x;

    const float* Asrc = (ct < 4) ? Wq : (ct < 8) ? Wv : (ct == 8) ? Wq : Wk;
    #pragma unroll
    for (int it = 0; it < 4; it++) {
        int idx = tid + it * 256;
        int i = idx >> 5, c4 = (idx & 31) * 4;
        *(float4*)(As + i * 132 + c4) = *(const float4*)(Asrc + (r0 + i) * 128 + c4);
    }
    if (ct < 4) {
        // Bs[c][m] = Wk[(ct*32+c)*128 + m]  (row copy, coalesced)
        #pragma unroll
        for (int it = 0; it < 4; it++) {
            int idx = tid + it * 256;
            int c = idx >> 5, m4 = (idx & 31) * 4;
            *(float4*)(Bs + c * 132 + m4) = *(const float4*)(Wk + (ct * 32 + c) * 128 + m4);
        }
    } else if (ct < 8) {
        // Bs[c][m] = Wth[m*128 + (ct-4)*32 + c]
        #pragma unroll
        for (int it = 0; it < 4; it++) {
            int idx = tid + it * 256;
            int m = idx >> 3, c4 = (idx & 7) * 4;
            float4 v = *(const float4*)(Wth + m * 128 + (ct - 4) * 32 + c4);
            Bs[(c4 + 0) * 132 + m] = v.x;
            Bs[(c4 + 1) * 132 + m] = v.y;
            Bs[(c4 + 2) * 132 + m] = v.z;
            Bs[(c4 + 3) * 132 + m] = v.w;
        }
    } else {
        int off = (ct == 9) ? 128 : 0;
        #pragma unroll
        for (int it = 0; it < 4; it++) {
            int idx = tid + it * 256;
            int m = idx >> 3, c4 = (idx & 7) * 4;
            float4 v = *(const float4*)(W1 + (off + m) * 32 + c4);
            Bs[(c4 + 0) * 132 + m] = v.x;
            Bs[(c4 + 1) * 132 + m] = v.y;
            Bs[(c4 + 2) * 132 + m] = v.z;
            Bs[(c4 + 3) * 132 + m] = v.w;
        }
    }
    __syncthreads();

    int tx = tid & 15, ty = tid >> 4;
    u64 a00 = 0, a01 = 0, a10 = 0, a11 = 0;
    #pragma unroll 8
    for (int m = 0; m < 128; m += 4) {
        float4 x0 = *(float4*)(As + (ty * 2 + 0) * 132 + m);
        float4 x1 = *(float4*)(As + (ty * 2 + 1) * 132 + m);
        float4 y0 = *(float4*)(Bs + (tx * 2 + 0) * 132 + m);
        float4 y1 = *(float4*)(Bs + (tx * 2 + 1) * 132 + m);
        u64 x0a = pk2(x0.x, x0.y), x0b = pk2(x0.z, x0.w);
        u64 x1a = pk2(x1.x, x1.y), x1b = pk2(x1.z, x1.w);
        u64 y0a = pk2(y0.x, y0.y), y0b = pk2(y0.z, y0.w);
        u64 y1a = pk2(y1.x, y1.y), y1b = pk2(y1.z, y1.w);
        a00 = fma2_(x0a, y0a, a00); a00 = fma2_(x0b, y0b, a00);
        a01 = fma2_(x0a, y1a, a01); a01 = fma2_(x0b, y1b, a01);
        a10 = fma2_(x1a, y0a, a10); a10 = fma2_(x1b, y0b, a10);
        a11 = fma2_(x1a, y1a, a11); a11 = fma2_(x1b, y1b, a11);
    }
    float2 f;
    int orow = r0 + ty * 2, ocol = ct * 32 + tx * 2;
    f = up2(a00); g_Wcat[(orow + 0) * SCOLS + ocol + 0] = f.x + f.y;
    f = up2(a01); g_Wcat[(orow + 0) * SCOLS + ocol + 1] = f.x + f.y;
    f = up2(a10); g_Wcat[(orow + 1) * SCOLS + ocol + 0] = f.x + f.y;
    f = up2(a11); g_Wcat[(orow + 1) * SCOLS + ocol + 1] = f.x + f.y;
}

// ---------------- K1: S1 = Z @ Wcat via 3xTF32 tensor cores ----------------
__device__ __forceinline__ uint32_t f2tf(float f) {
    uint32_t u; asm("cvt.rna.tf32.f32 %0, %1;" : "=r"(u) : "f"(f)); return u;
}
__device__ __forceinline__ void mma_tf32(float* c, const uint32_t* a, const uint32_t* b) {
    asm volatile("mma.sync.aligned.m16n8k8.row.col.f32.tf32.tf32.f32 "
        "{%0,%1,%2,%3}, {%4,%5,%6,%7}, {%8,%9}, {%0,%1,%2,%3};"
        : "+f"(c[0]), "+f"(c[1]), "+f"(c[2]), "+f"(c[3])
        : "r"(a[0]), "r"(a[1]), "r"(a[2]), "r"(a[3]), "r"(b[0]), "r"(b[1]));
}

#define K1_SMEM ((128*36*2 + 32*136*2) * 4)

__global__ void __launch_bounds__(256) k1_gemm(const float* __restrict__ x) {
    extern __shared__ uint32_t smk1[];
    uint32_t* Ah = smk1;                 // 128 x 36
    uint32_t* Al = Ah + 128 * 36;
    uint32_t* Bh = Al + 128 * 36;        // 32 x 136
    uint32_t* Bl = Bh + 32 * 136;

    int m0 = blockIdx.x * 128;
    int n0 = blockIdx.y * 128;
    int tid = threadIdx.x;
    int lane = tid & 31, warp = tid >> 5;
    int g = lane >> 2, t4 = lane & 3;
    int wm = warp >> 2, wn = warp & 3;   // 2 x 4 warp grid
    int mb = wm * 64, nb = wn * 32;

    float c[4][4][4];
    #pragma unroll
    for (int im = 0; im < 4; im++)
        #pragma unroll
        for (int in_ = 0; in_ < 4; in_++)
            #pragma unroll
            for (int q = 0; q < 4; q++) c[im][in_][q] = 0.f;

    for (int kk = 0; kk < 128; kk += 32) {
        #pragma unroll
        for (int it = 0; it < 4; it++) {
            int idx = tid + it * 256;
            int i = idx >> 3, c4 = (idx & 7) * 4;
            int r = m0 + i;
            int bt = r >> 6, n = r & 63;
            int b = bt / 96, t = bt - b * 96;
            float4 v = *(const float4*)(x + (size_t)(((b * 64 + n) * 96 + t)) * 128 + kk + c4);
            float vv[4] = {v.x, v.y, v.z, v.w};
            #pragma unroll
            for (int q = 0; q < 4; q++) {
                uint32_t hi = f2tf(vv[q]);
                float lof = vv[q] - __uint_as_float(hi);
                Ah[i * 36 + c4 + q] = hi;
                Al[i * 36 + c4 + q] = f2tf(lof);
            }
        }
        #pragma unroll
        for (int it = 0; it < 4; it++) {
            int idx = tid + it * 256;
            int kr = idx >> 5, c4 = (idx & 31) * 4;
            int col = n0 + c4;
            float4 v = make_float4(0.f, 0.f, 0.f, 0.f);
            if (col < SCOLS) v = *(const float4*)(g_Wcat + (kk + kr) * SCOLS + col);
            float vv[4] = {v.x, v.y, v.z, v.w};
            #pragma unroll
            for (int q = 0; q < 4; q++) {
                uint32_t hi = f2tf(vv[q]);
                float lof = vv[q] - __uint_as_float(hi);
                Bh[kr * 136 + c4 + q] = hi;
                Bl[kr * 136 + c4 + q] = f2tf(lof);
            }
        }
        __syncthreads();

        #pragma unroll
        for (int ks = 0; ks < 4; ks++) {
            int k0 = ks * 8;
            uint32_t ahi[4][4], alo[4][4], bhi[4][2], blo[4][2];
            #pragma unroll
            for (int im = 0; im < 4; im++) {
                int rA = (mb + im * 16 + g) * 36 + k0 + t4;
                int rA8 = rA + 8 * 36;
                ahi[im][0] = Ah[rA];      ahi[im][1] = Ah[rA8];
                ahi[im][2] = Ah[rA + 4];  ahi[im][3] = Ah[rA8 + 4];
                alo[im][0] = Al[rA];      alo[im][1] = Al[rA8];
                alo[im][2] = Al[rA + 4];  alo[im][3] = Al[rA8 + 4];
            }
            #pragma unroll
            for (int in_ = 0; in_ < 4; in_++) {
                int colB = nb + in_ * 8 + g;
                bhi[in_][0] = Bh[(k0 + t4) * 136 + colB];
                bhi[in_][1] = Bh[(k0 + t4 + 4) * 136 + colB];
                blo[in_][0] = Bl[(k0 + t4) * 136 + colB];
                blo[in_][1] = Bl[(k0 + t4 + 4) * 136 + colB];
            }
            #pragma unroll
            for (int im = 0; im < 4; im++)
                #pragma unroll
                for (int in_ = 0; in_ < 4; in_++) {
                    mma_tf32(c[im][in_], ahi[im], bhi[in_]);
                    mma_tf32(c[im][in_], alo[im], bhi[in_]);
                    mma_tf32(c[im][in_], ahi[im], blo[in_]);
                }
        }
        __syncthreads();
    }

    #pragma unroll
    for (int im = 0; im < 4; im++)
        #pragma unroll
        for (int in_ = 0; in_ < 4; in_++) {
            int row = m0 + mb + im * 16 + g;
            int col = n0 + nb + in_ * 8 + t4 * 2;
            if (col < SCOLS) {
                *(float2*)(g_S1 + (size_t)row * SCOLS + col) = make_float2(c[im][in_][0], c[im][in_][1]);
                *(float2*)(g_S1 + (size_t)(row + 8) * SCOLS + col) = make_float2(c[im][in_][2], c[im][in_][3]);
            }
        }
}

// ---------------- K2: fused attention, 1 block per bt, 2 blocks/SM, f32x2 math ----------------
#define K2_SMEM ((64*132 + 64*132 + 64*32 + 64*36 + 64*64 + 128 + 32 + 32 + 128 + 128 + 8 + 64) * 4)

__global__ void __launch_bounds__(256, 2) k2_attn(
    const float* __restrict__ x, const float* __restrict__ edge,
    const float* __restrict__ prior, const unsigned char* __restrict__ maskp,
    const float* __restrict__ W1, const float* __restrict__ b1,
    const float* __restrict__ W2, const float* __restrict__ b2,
    const float* __restrict__ Wfuse, const float* __restrict__ lng,
    const float* __restrict__ lnb, const float* __restrict__ pw,
    const float* __restrict__ prw, float* __restrict__ out) {
    extern __shared__ float sm[];
    float* Zs   = sm;               // 64*132
    float* Gs   = Zs + 64 * 132;    // 64*132 (reused as h)
    float* qhs  = Gs + 64 * 132;    // 64*32  (qh + b1 pre-added)  } overlay: alphaT 64*68
    float* khs  = qhs + 64 * 32;    // 64*36                        }
    float* Ls   = khs + 64 * 36;    // 64*64
    float* W1qs = Ls + 64 * 64;     // 4*32  (edge-proj rows, t-major per q)
    float* b1s  = W1qs + 128;       // 32
    float* W2s  = b1s + 32;         // 32
    float* lngs = W2s + 32;         // 128
    float* lnbs = lngs + 128;       // 128
    float* Wfs  = lnbs + 128;       // 8
    float* msk  = Wfs + 8;          // 64
    float* alphaT = qhs;            // 64*68

    int bt = blockIdx.x;
    int b = bt / 96, t = bt - b * 96;
    int tid = threadIdx.x;
    int warp = tid >> 5, lane = tid & 31;

    // ---- Phase A: loads ----
    const float* xbase = x + (size_t)((b * 64) * 96 + t) * 128;
    const float* s1 = g_S1 + (size_t)(bt * 64) * SCOLS;
    #pragma unroll
    for (int it = 0; it < 8; it++) {
        int idx = tid + it * 256;
        int i = idx >> 5, c4 = (idx & 31) * 4;
        *(float4*)(Zs + i * 132 + c4) = *(const float4*)(xbase + (size_t)i * 96 * 128 + c4);
        *(float4*)(Gs + i * 132 + c4) = *(const float4*)(s1 + (size_t)i * SCOLS + c4);
    }
    #pragma unroll
    for (int it = 0; it < 2; it++) {
        int idx = tid + it * 256;
        int i = idx >> 3, c4 = (idx & 7) * 4;
        *(float4*)(qhs + i * 32 + c4) = *(const float4*)(s1 + (size_t)i * SCOLS + 256 + c4);
        *(float4*)(khs + i * 36 + c4) = *(const float4*)(s1 + (size_t)i * SCOLS + 288 + c4);
    }
    if (tid < 128) {
        int q = tid >> 5, tt = tid & 31;
        W1qs[q * 32 + tt] = W1[(256 + q) * 32 + tt];
        lngs[tid] = lng[tid];
        lnbs[tid] = lnb[tid];
    }
    if (tid < 32) { b1s[tid] = b1[tid]; W2s[tid] = W2[tid]; }
    if (tid < 5) Wfs[tid] = Wfuse[tid];
    if (tid < 64) msk[tid] = (float)maskp[b * 64 + tid];
    __syncthreads();
    // fold b1 into qhs
    #pragma unroll
    for (int it = 0; it < 8; it++) {
        int idx = tid + it * 256;
        qhs[idx] += b1s[idx & 31];
    }
    __syncthreads();

    float pwv = pw[0], prwv = prw[0], b2v = b2[0];

    // ---- Phase B: logits, 4x4 register tile per thread, packed f32x2 ----
    int ti = tid >> 4, tj = tid & 15;
    int i0 = ti * 4, j0 = tj * 4;
    u64 cc2[4][4];
    #pragma unroll
    for (int u = 0; u < 4; u++)
        #pragma unroll
        for (int v = 0; v < 4; v++) cc2[u][v] = 0ULL;
    #pragma unroll 4
    for (int d4 = 0; d4 < 128; d4 += 4) {
        u64 ga[4], gb[4], za[4], zb[4];
        #pragma unroll
        for (int u = 0; u < 4; u++) {
            float4 g4 = *(float4*)(Gs + (i0 + u) * 132 + d4);
            ga[u] = pk2(g4.x, g4.y); gb[u] = pk2(g4.z, g4.w);
        }
        #pragma unroll
        for (int v = 0; v < 4; v++) {
            float4 z4 = *(float4*)(Zs + (j0 + v) * 132 + d4);
            za[v] = pk2(z4.x, z4.y); zb[v] = pk2(z4.z, z4.w);
        }
        #pragma unroll
        for (int u = 0; u < 4; u++)
            #pragma unroll
            for (int v = 0; v < 4; v++) {
                cc2[u][v] = fma2_(ga[u], za[v], cc2[u][v]);
                cc2[u][v] = fma2_(gb[u], zb[v], cc2[u][v]);
            }
    }
    float cc[4][4];
    #pragma unroll
    for (int u = 0; u < 4; u++)
        #pragma unroll
        for (int v = 0; v < 4; v++) { float2 f = up2(cc2[u][v]); cc[u][v] = f.x + f.y; }

    const float* ebase = edge + (size_t)bt * 4096 * 4;
    const float* pbase = prior + (size_t)bt * 4096 * 5;
    #pragma unroll 1
    for (int u = 0; u < 4; u++) {
        int i = i0 + u;
        // edge features for the 4 j's, packed broadcast pairs
        u64 ex2[4], ey2[4], ez2[4], ew2[4];
        #pragma unroll
        for (int j = 0; j < 4; j++) {
            float4 e = *(const float4*)(ebase + (size_t)(i * 64 + j0 + j) * 4);
            ex2[j] = pk2(e.x, e.x); ey2[j] = pk2(e.y, e.y);
            ez2[j] = pk2(e.z, e.z); ew2[j] = pk2(e.w, e.w);
        }
        float p0 = 0.f, p1 = 0.f, p2 = 0.f, p3 = 0.f;
        #pragma unroll
        for (int t4 = 0; t4 < 32; t4 += 4) {
            float4 qb = *(float4*)(qhs + i * 32 + t4);
            float4 w2v = *(float4*)(W2s + t4);
            float4 wq0 = *(float4*)(W1qs + 0 * 32 + t4);
            float4 wq1 = *(float4*)(W1qs + 1 * 32 + t4);
            float4 wq2 = *(float4*)(W1qs + 2 * 32 + t4);
            float4 wq3 = *(float4*)(W1qs + 3 * 32 + t4);
            u64 qba = pk2(qb.x, qb.y), qbb = pk2(qb.z, qb.w);
            u64 w0a = pk2(wq0.x, wq0.y), w0b = pk2(wq0.z, wq0.w);
            u64 w1a = pk2(wq1.x, wq1.y), w1b = pk2(wq1.z, wq1.w);
            u64 w2a = pk2(wq2.x, wq2.y), w2b = pk2(wq2.z, wq2.w);
            u64 w3a = pk2(wq3.x, wq3.y), w3b = pk2(wq3.z, wq3.w);
            float* pp[4] = {&p0, &p1, &p2, &p3};
            #pragma unroll
            for (int j = 0; j < 4; j++) {
                float4 kh = *(float4*)(khs + (j0 + j) * 36 + t4);
                u64 h01 = add2_(qba, pk2(kh.x, kh.y));
                h01 = fma2_(ex2[j], w0a, h01);
                h01 = fma2_(ey2[j], w1a, h01);
                h01 = fma2_(ez2[j], w2a, h01);
                h01 = fma2_(ew2[j], w3a, h01);
                float2 hf = up2(h01);
                float pj = *pp[j];
                pj = fmaf(fmaxf(hf.x, 0.f), w2v.x, pj);
                pj = fmaf(fmaxf(hf.y, 0.f), w2v.y, pj);
                u64 h23 = add2_(qbb, pk2(kh.z, kh.w));
                h23 = fma2_(ex2[j], w0b, h23);
                h23 = fma2_(ey2[j], w1b, h23);
                h23 = fma2_(ez2[j], w2b, h23);
                h23 = fma2_(ew2[j], w3b, h23);
                hf = up2(h23);
                pj = fmaf(fmaxf(hf.x, 0.f), w2v.z, pj);
                pj = fmaf(fmaxf(hf.y, 0.f), w2v.w, pj);
                *pp[j] = pj;
            }
        }
        // prior: 20 consecutive floats -> 5 LDG.128
        float pr[20];
        const float* ap0 = pbase + (size_t)(i * 64 + j0) * 5;
        *(float4*)(pr + 0)  = *(const float4*)(ap0 + 0);
        *(float4*)(pr + 4)  = *(const float4*)(ap0 + 4);
        *(float4*)(pr + 8)  = *(const float4*)(ap0 + 8);
        *(float4*)(pr + 12) = *(const float4*)(ap0 + 12);
        *(float4*)(pr + 16) = *(const float4*)(ap0 + 16);
        float phys[4] = {p0, p1, p2, p3};
        float Lv[4];
        #pragma unroll
        for (int v = 0; v < 4; v++) {
            float Ap = pr[v*5+0]*Wfs[0] + pr[v*5+1]*Wfs[1] + pr[v*5+2]*Wfs[2]
                     + pr[v*5+3]*Wfs[3] + pr[v*5+4]*Wfs[4];
            Ap = fmaxf(Ap, 0.f);
            float L = cc[u][v] * 0.08838834764831845f + pwv * (phys[v] + b2v)
                      + prwv * __logf(Ap + 1e-6f);
            if (msk[i] != 0.f || msk[j0 + v] != 0.f) L = -1e9f;
            Lv[v] = L;
        }
        *(float4*)(Ls + i * 64 + j0) = make_float4(Lv[0], Lv[1], Lv[2], Lv[3]);
    }
    __syncthreads();

    // ---- Phase C: softmax per row, write transposed alpha (overlays qhs/khs) ----
    #pragma unroll 1
    for (int rr = 0; rr < 8; rr++) {
        int r = warp + rr * 8;
        float v0 = Ls[r * 64 + lane], v1 = Ls[r * 64 + lane + 32];
        float m = fmaxf(v0, v1);
        #pragma unroll
        for (int o = 16; o; o >>= 1) m = fmaxf(m, __shfl_xor_sync(0xffffffffu, m, o));
        float e0 = __expf(v0 - m), e1 = __expf(v1 - m);
        float s = e0 + e1;
        #pragma unroll
        for (int o = 16; o; o >>= 1) s += __shfl_xor_sync(0xffffffffu, s, o);
        float inv = 1.f / s;
        alphaT[lane * 68 + r] = e0 * inv;
        alphaT[(lane + 32) * 68 + r] = e1 * inv;
    }
    __syncthreads();

    // ---- Phase D: h = Z + alpha @ Vt (V streamed from L2), packed ----
    int di = tid & 127, grp = tid >> 7;
    const float* vrow = g_S1 + (size_t)(bt * 64) * SCOLS + 128 + di;
    #pragma unroll 1
    for (int it = 0; it < 2; it++) {
        int r0 = grp * 32 + it * 16;
        u64 acc2[8];
        #pragma unroll
        for (int q = 0; q < 8; q++)
            acc2[q] = pk2(Zs[(r0 + 2*q) * 132 + di], Zs[(r0 + 2*q + 1) * 132 + di]);
        #pragma unroll 4
        for (int jj = 0; jj < 64; jj++) {
            float vv = __ldg(vrow + (size_t)jj * SCOLS);
            u64 vv2 = pk2(vv, vv);
            float4 a0 = *(float4*)(alphaT + jj * 68 + r0);
            float4 a1 = *(float4*)(alphaT + jj * 68 + r0 + 4);
            float4 a2 = *(float4*)(alphaT + jj * 68 + r0 + 8);
            float4 a3 = *(float4*)(alphaT + jj * 68 + r0 + 12);
            acc2[0] = fma2_(pk2(a0.x, a0.y), vv2, acc2[0]);
            acc2[1] = fma2_(pk2(a0.z, a0.w), vv2, acc2[1]);
            acc2[2] = fma2_(pk2(a1.x, a1.y), vv2, acc2[2]);
            acc2[3] = fma2_(pk2(a1.z, a1.w), vv2, acc2[3]);
            acc2[4] = fma2_(pk2(a2.x, a2.y), vv2, acc2[4]);
            acc2[5] = fma2_(pk2(a2.z, a2.w), vv2, acc2[5]);
            acc2[6] = fma2_(pk2(a3.x, a3.y), vv2, acc2[6]);
            acc2[7] = fma2_(pk2(a3.z, a3.w), vv2, acc2[7]);
        }
        #pragma unroll
        for (int q = 0; q < 8; q++) {
            float2 f = up2(acc2[q]);
            Gs[(r0 + 2*q) * 132 + di] = f.x;
            Gs[(r0 + 2*q + 1) * 132 + di] = f.y;
        }
    }
    __syncthreads();

    // ---- Phase E: LayerNorm + masked, transposed store ----
    float* outb = out + (size_t)((b * 64) * 96 + t) * 128;
    #pragma unroll 1
    for (int rr = 0; rr < 8; rr++) {
        int r = warp + rr * 8;
        float v[4];
        #pragma unroll
        for (int u = 0; u < 4; u++) v[u] = Gs[r * 132 + lane + 32 * u];
        float s = v[0] + v[1] + v[2] + v[3];
        #pragma unroll
        for (int o = 16; o; o >>= 1) s += __shfl_xor_sync(0xffffffffu, s, o);
        float mu = s * (1.f / 128.f);
        float q = 0.f;
        #pragma unroll
        for (int u = 0; u < 4; u++) { float d = v[u] - mu; q = fmaf(d, d, q); }
        #pragma unroll
        for (int o = 16; o; o >>= 1) q += __shfl_xor_sync(0xffffffffu, q, o);
        float inv = rsqrtf(q * (1.f / 128.f) + 1e-5f);
        float keep = (msk[r] != 0.f) ? 0.f : 1.f;
        float* op = outb + (size_t)r * 96 * 128;
        #pragma unroll
        for (int u = 0; u < 4; u++) {
            int d = lane + 32 * u;
            op[d] = ((v[u] - mu) * inv * lngs[d] + lnbs[d]) * keep;
        }
    }
}

extern "C" void kernel_launch(void* const* d_in, const int* in_sizes, int n_in,
                              void* d_out, int out_size) {
    const float* x     = (const float*)d_in[0];
    const float* edge  = (const float*)d_in[1];
    const float* prior = (const float*)d_in[2];
    const unsigned char* maskp = (const unsigned char*)d_in[3];
    const float* Wq    = (const float*)d_in[4];
    const float* Wk    = (const float*)d_in[5];
    const float* Wv    = (const float*)d_in[6];
    const float* W1    = (const float*)d_in[7];
    const float* b1    = (const float*)d_in[8];
    const float* W2    = (const float*)d_in[9];
    const float* b2    = (const float*)d_in[10];
    const float* Wfuse = (const float*)d_in[11];
    const float* Wth   = (const float*)d_in[12];
    const float* lng   = (const float*)d_in[13];
    const float* lnb   = (const float*)d_in[14];
    const float* pw    = (const float*)d_in[15];
    const float* prw   = (const float*)d_in[16];
    float* out = (float*)d_out;

    static int inited = 0;
    if (!inited) {
        cudaFuncSetAttribute(k1_gemm, cudaFuncAttributeMaxDynamicSharedMemorySize, K1_SMEM);
        cudaFuncSetAttribute(k2_attn, cudaFuncAttributeMaxDynamicSharedMemorySize, K2_SMEM);
        inited = 1;
    }

    k0_fuse<<<dim3(10, 4), 256>>>(Wq, Wk, Wv, W1, Wth);
    k1_gemm<<<dim3(96, 3), 256, K1_SMEM>>>(x);
    k2_attn<<<192, 256, K2_SMEM>>>(x, edge, prior, maskp, W1, b1, W2, b2,
                                   Wfuse, lng, lnb, pw, prw, out);
}

// round 9
// speedup vs baseline: 1.4987x; 1.2553x over previous
#include <cuda_runtime.h>
#include <cstdint>

#define BT_TOT 192
#define NN 64
#define DM 128
#define TT 96
#define SCOLS 320   // 0-127: G=Z@(Wq Wk^T), 128-255: Vt=Z@(Wv Wth), 256-287: qh, 288-319: kh

__device__ float g_Wcat[128 * SCOLS];
__device__ float g_S1[12288 * SCOLS];
__device__ float g_C[192 * 64 * 64];   // content logits (pre-scaled)

typedef unsigned long long u64;
__device__ __forceinline__ u64 pk2(float lo, float hi) {
    u64 r; asm("mov.b64 %0,{%1,%2};" : "=l"(r) : "f"(lo), "f"(hi)); return r;
}
__device__ __forceinline__ float2 up2(u64 v) {
    float2 f; asm("mov.b64 {%0,%1},%2;" : "=f"(f.x), "=f"(f.y) : "l"(v)); return f;
}
__device__ __forceinline__ u64 fma2_(u64 a, u64 b, u64 c) {
    u64 d; asm("fma.rn.f32x2 %0,%1,%2,%3;" : "=l"(d) : "l"(a), "l"(b), "l"(c)); return d;
}
__device__ __forceinline__ u64 add2_(u64 a, u64 b) {
    u64 d; asm("add.rn.f32x2 %0,%1,%2;" : "=l"(d) : "l"(a), "l"(b)); return d;
}

// ---------------- K0: fuse weights into g_Wcat ----------------
__global__ void __launch_bounds__(256) k0_fuse(
    const float* __restrict__ Wq, const float* __restrict__ Wk,
    const float* __restrict__ Wv, const float* __restrict__ W1,
    const float* __restrict__ Wth) {
    __shared__ float As[32 * 132];   // [row][m]
    __shared__ float Bs[32 * 132];   // [col][m]
    int ct = blockIdx.x;   // 0..9
    int rt = blockIdx.y;   // 0..3
    int r0 = rt * 32;
    int tid = threadIdx.x;

    const float* Asrc = (ct < 4) ? Wq : (ct < 8) ? Wv : (ct == 8) ? Wq : Wk;
    #pragma unroll
    for (int it = 0; it < 4; it++) {
        int idx = tid + it * 256;
        int i = idx >> 5, c4 = (idx & 31) * 4;
        *(float4*)(As + i * 132 + c4) = *(const float4*)(Asrc + (r0 + i) * 128 + c4);
    }
    if (ct < 4) {
        #pragma unroll
        for (int it = 0; it < 4; it++) {
            int idx = tid + it * 256;
            int c = idx >> 5, m4 = (idx & 31) * 4;
            *(float4*)(Bs + c * 132 + m4) = *(const float4*)(Wk + (ct * 32 + c) * 128 + m4);
        }
    } else if (ct < 8) {
        #pragma unroll
        for (int it = 0; it < 4; it++) {
            int idx = tid + it * 256;
            int m = idx >> 3, c4 = (idx & 7) * 4;
            float4 v = *(const float4*)(Wth + m * 128 + (ct - 4) * 32 + c4);
            Bs[(c4 + 0) * 132 + m] = v.x;
            Bs[(c4 + 1) * 132 + m] = v.y;
            Bs[(c4 + 2) * 132 + m] = v.z;
            Bs[(c4 + 3) * 132 + m] = v.w;
        }
    } else {
        int off = (ct == 9) ? 128 : 0;
        #pragma unroll
        for (int it = 0; it < 4; it++) {
            int idx = tid + it * 256;
            int m = idx >> 3, c4 = (idx & 7) * 4;
            float4 v = *(const float4*)(W1 + (off + m) * 32 + c4);
            Bs[(c4 + 0) * 132 + m] = v.x;
            Bs[(c4 + 1) * 132 + m] = v.y;
            Bs[(c4 + 2) * 132 + m] = v.z;
            Bs[(c4 + 3) * 132 + m] = v.w;
        }
    }
    __syncthreads();

    int tx = tid & 15, ty = tid >> 4;
    u64 a00 = 0, a01 = 0, a10 = 0, a11 = 0;
    #pragma unroll 8
    for (int m = 0; m < 128; m += 4) {
        float4 x0 = *(float4*)(As + (ty * 2 + 0) * 132 + m);
        float4 x1 = *(float4*)(As + (ty * 2 + 1) * 132 + m);
        float4 y0 = *(float4*)(Bs + (tx * 2 + 0) * 132 + m);
        float4 y1 = *(float4*)(Bs + (tx * 2 + 1) * 132 + m);
        u64 x0a = pk2(x0.x, x0.y), x0b = pk2(x0.z, x0.w);
        u64 x1a = pk2(x1.x, x1.y), x1b = pk2(x1.z, x1.w);
        u64 y0a = pk2(y0.x, y0.y), y0b = pk2(y0.z, y0.w);
        u64 y1a = pk2(y1.x, y1.y), y1b = pk2(y1.z, y1.w);
        a00 = fma2_(x0a, y0a, a00); a00 = fma2_(x0b, y0b, a00);
        a01 = fma2_(x0a, y1a, a01); a01 = fma2_(x0b, y1b, a01);
        a10 = fma2_(x1a, y0a, a10); a10 = fma2_(x1b, y0b, a10);
        a11 = fma2_(x1a, y1a, a11); a11 = fma2_(x1b, y1b, a11);
    }
    float2 f;
    int orow = r0 + ty * 2, ocol = ct * 32 + tx * 2;
    f = up2(a00); g_Wcat[(orow + 0) * SCOLS + ocol + 0] = f.x + f.y;
    f = up2(a01); g_Wcat[(orow + 0) * SCOLS + ocol + 1] = f.x + f.y;
    f = up2(a10); g_Wcat[(orow + 1) * SCOLS + ocol + 0] = f.x + f.y;
    f = up2(a11); g_Wcat[(orow + 1) * SCOLS + ocol + 1] = f.x + f.y;
}

// ---------------- TF32 helpers ----------------
__device__ __forceinline__ uint32_t f2tf(float f) {
    uint32_t u; asm("cvt.rna.tf32.f32 %0, %1;" : "=r"(u) : "f"(f)); return u;
}
__device__ __forceinline__ void mma_tf32(float* c, const uint32_t* a, const uint32_t* b) {
    asm volatile("mma.sync.aligned.m16n8k8.row.col.f32.tf32.tf32.f32 "
        "{%0,%1,%2,%3}, {%4,%5,%6,%7}, {%8,%9}, {%0,%1,%2,%3};"
        : "+f"(c[0]), "+f"(c[1]), "+f"(c[2]), "+f"(c[3])
        : "r"(a[0]), "r"(a[1]), "r"(a[2]), "r"(a[3]), "r"(b[0]), "r"(b[1]));
}

// ---------------- K1: S1 = Z @ Wcat via 3xTF32 tensor cores ----------------
#define K1_SMEM ((128*36*2 + 32*136*2) * 4)

__global__ void __launch_bounds__(256) k1_gemm(const float* __restrict__ x) {
    extern __shared__ uint32_t smk1[];
    uint32_t* Ah = smk1;                 // 128 x 36
    uint32_t* Al = Ah + 128 * 36;
    uint32_t* Bh = Al + 128 * 36;        // 32 x 136
    uint32_t* Bl = Bh + 32 * 136;

    int m0 = blockIdx.x * 128;
    int n0 = blockIdx.y * 128;
    int tid = threadIdx.x;
    int lane = tid & 31, warp = tid >> 5;
    int g = lane >> 2, t4 = lane & 3;
    int wm = warp >> 2, wn = warp & 3;
    int mb = wm * 64, nb = wn * 32;

    float c[4][4][4];
    #pragma unroll
    for (int im = 0; im < 4; im++)
        #pragma unroll
        for (int in_ = 0; in_ < 4; in_++)
            #pragma unroll
            for (int q = 0; q < 4; q++) c[im][in_][q] = 0.f;

    for (int kk = 0; kk < 128; kk += 32) {
        #pragma unroll
        for (int it = 0; it < 4; it++) {
            int idx = tid + it * 256;
            int i = idx >> 3, c4 = (idx & 7) * 4;
            int r = m0 + i;
            int bt = r >> 6, n = r & 63;
            int b = bt / 96, t = bt - b * 96;
            float4 v = *(const float4*)(x + (size_t)(((b * 64 + n) * 96 + t)) * 128 + kk + c4);
            float vv[4] = {v.x, v.y, v.z, v.w};
            #pragma unroll
            for (int q = 0; q < 4; q++) {
                uint32_t hi = f2tf(vv[q]);
                float lof = vv[q] - __uint_as_float(hi);
                Ah[i * 36 + c4 + q] = hi;
                Al[i * 36 + c4 + q] = f2tf(lof);
            }
        }
        #pragma unroll
        for (int it = 0; it < 4; it++) {
            int idx = tid + it * 256;
            int kr = idx >> 5, c4 = (idx & 31) * 4;
            int col = n0 + c4;
            float4 v = make_float4(0.f, 0.f, 0.f, 0.f);
            if (col < SCOLS) v = *(const float4*)(g_Wcat + (kk + kr) * SCOLS + col);
            float vv[4] = {v.x, v.y, v.z, v.w};
            #pragma unroll
            for (int q = 0; q < 4; q++) {
                uint32_t hi = f2tf(vv[q]);
                float lof = vv[q] - __uint_as_float(hi);
                Bh[kr * 136 + c4 + q] = hi;
                Bl[kr * 136 + c4 + q] = f2tf(lof);
            }
        }
        __syncthreads();

        #pragma unroll
        for (int ks = 0; ks < 4; ks++) {
            int k0 = ks * 8;
            uint32_t ahi[4][4], alo[4][4], bhi[4][2], blo[4][2];
            #pragma unroll
            for (int im = 0; im < 4; im++) {
                int rA = (mb + im * 16 + g) * 36 + k0 + t4;
                int rA8 = rA + 8 * 36;
                ahi[im][0] = Ah[rA];      ahi[im][1] = Ah[rA8];
                ahi[im][2] = Ah[rA + 4];  ahi[im][3] = Ah[rA8 + 4];
                alo[im][0] = Al[rA];      alo[im][1] = Al[rA8];
                alo[im][2] = Al[rA + 4];  alo[im][3] = Al[rA8 + 4];
            }
            #pragma unroll
            for (int in_ = 0; in_ < 4; in_++) {
                int colB = nb + in_ * 8 + g;
                bhi[in_][0] = Bh[(k0 + t4) * 136 + colB];
                bhi[in_][1] = Bh[(k0 + t4 + 4) * 136 + colB];
                blo[in_][0] = Bl[(k0 + t4) * 136 + colB];
                blo[in_][1] = Bl[(k0 + t4 + 4) * 136 + colB];
            }
            #pragma unroll
            for (int im = 0; im < 4; im++)
                #pragma unroll
                for (int in_ = 0; in_ < 4; in_++) {
                    mma_tf32(c[im][in_], ahi[im], bhi[in_]);
                    mma_tf32(c[im][in_], alo[im], bhi[in_]);
                    mma_tf32(c[im][in_], ahi[im], blo[in_]);
                }
        }
        __syncthreads();
    }

    #pragma unroll
    for (int im = 0; im < 4; im++)
        #pragma unroll
        for (int in_ = 0; in_ < 4; in_++) {
            int row = m0 + mb + im * 16 + g;
            int col = n0 + nb + in_ * 8 + t4 * 2;
            if (col < SCOLS) {
                *(float2*)(g_S1 + (size_t)row * SCOLS + col) = make_float2(c[im][in_][0], c[im][in_][1]);
                *(float2*)(g_S1 + (size_t)(row + 8) * SCOLS + col) = make_float2(c[im][in_][2], c[im][in_][3]);
            }
        }
}

// ---------------- K1B: content[bt] = G @ Z^T (scaled), 3xTF32 ----------------
#define K1B_SMEM ((64*136*2 + 32*136*2) * 4)

__global__ void __launch_bounds__(256) k1b_content(const float* __restrict__ x) {
    extern __shared__ uint32_t smc[];
    uint32_t* Gh = smc;                  // 64 x 136
    uint32_t* Gl = Gh + 64 * 136;
    uint32_t* Zh = Gl + 64 * 136;        // 32 x 136
    uint32_t* Zl = Zh + 32 * 136;

    int bt = blockIdx.x;
    int b = bt / 96, t = bt - b * 96;
    int tid = threadIdx.x;
    int lane = tid & 31, warp = tid >> 5;
    int g = lane >> 2, t4 = lane & 3;
    int wi = warp >> 1, wj = warp & 1;

    // load G (rows bt*64.., cols 0..127 of g_S1), convert to tf32 hi/lo
    const float* s1 = g_S1 + (size_t)(bt * 64) * SCOLS;
    #pragma unroll
    for (int it = 0; it < 8; it++) {
        int idx = tid + it * 256;
        int i = idx >> 5, c4 = (idx & 31) * 4;
        float4 v = *(const float4*)(s1 + (size_t)i * SCOLS + c4);
        float vv[4] = {v.x, v.y, v.z, v.w};
        #pragma unroll
        for (int q = 0; q < 4; q++) {
            uint32_t hi = f2tf(vv[q]);
            float lof = vv[q] - __uint_as_float(hi);
            Gh[i * 136 + c4 + q] = hi;
            Gl[i * 136 + c4 + q] = f2tf(lof);
        }
    }

    const float scale = 0.08838834764831845f;
    float* cbase = g_C + (size_t)bt * 4096;

    for (int jh = 0; jh < 2; jh++) {
        __syncthreads();
        // load Z half rows jh*32..+31 from x
        #pragma unroll
        for (int it = 0; it < 4; it++) {
            int idx = tid + it * 256;
            int j = idx >> 5, c4 = (idx & 31) * 4;
            float4 v = *(const float4*)(x + (size_t)(((b * 64 + jh * 32 + j) * 96 + t)) * 128 + c4);
            float vv[4] = {v.x, v.y, v.z, v.w};
            #pragma unroll
            for (int q = 0; q < 4; q++) {
                uint32_t hi = f2tf(vv[q]);
                float lof = vv[q] - __uint_as_float(hi);
                Zh[j * 136 + c4 + q] = hi;
                Zl[j * 136 + c4 + q] = f2tf(lof);
            }
        }
        __syncthreads();

        float c[2][4];
        #pragma unroll
        for (int n8 = 0; n8 < 2; n8++)
            #pragma unroll
            for (int q = 0; q < 4; q++) c[n8][q] = 0.f;

        #pragma unroll 4
        for (int k0 = 0; k0 < 128; k0 += 8) {
            uint32_t ah[4], al[4];
            int rA = (wi * 16 + g) * 136 + k0 + t4;
            int rA8 = rA + 8 * 136;
            ah[0] = Gh[rA]; ah[1] = Gh[rA8]; ah[2] = Gh[rA + 4]; ah[3] = Gh[rA8 + 4];
            al[0] = Gl[rA]; al[1] = Gl[rA8]; al[2] = Gl[rA + 4]; al[3] = Gl[rA8 + 4];
            #pragma unroll
            for (int n8 = 0; n8 < 2; n8++) {
                uint32_t bh[2], bl[2];
                int rB = (wj * 16 + n8 * 8 + g) * 136 + k0 + t4;
                bh[0] = Zh[rB]; bh[1] = Zh[rB + 4];
                bl[0] = Zl[rB]; bl[1] = Zl[rB + 4];
                mma_tf32(c[n8], ah, bh);
                mma_tf32(c[n8], al, bh);
                mma_tf32(c[n8], ah, bl);
            }
        }

        #pragma unroll
        for (int n8 = 0; n8 < 2; n8++) {
            int j = jh * 32 + wj * 16 + n8 * 8 + t4 * 2;
            int i = wi * 16 + g;
            *(float2*)(cbase + (size_t)i * 64 + j) = make_float2(c[n8][0] * scale, c[n8][1] * scale);
            *(float2*)(cbase + (size_t)(i + 8) * 64 + j) = make_float2(c[n8][2] * scale, c[n8][3] * scale);
        }
    }
}

// ---------------- K2: fused attention, 384 half-blocks, occ 3 ----------------
#define K2_SMEM ((32*132 + 32*32 + 64*36 + 32*64 + 128 + 32 + 32 + 128 + 128 + 8 + 64) * 4)

__global__ void __launch_bounds__(256, 3) k2_attn(
    const float* __restrict__ x, const float* __restrict__ edge,
    const float* __restrict__ prior, const unsigned char* __restrict__ maskp,
    const float* __restrict__ W1, const float* __restrict__ b1,
    const float* __restrict__ W2, const float* __restrict__ b2,
    const float* __restrict__ Wfuse, const float* __restrict__ lng,
    const float* __restrict__ lnb, const float* __restrict__ pw,
    const float* __restrict__ prw, float* __restrict__ out) {
    extern __shared__ float sm[];
    float* Zs   = sm;               // 32*132 (own i-half rows of Z; becomes h)
    float* qhs  = Zs + 32 * 132;    // 32*32  (qh + b1)   } overlay: alphaT 64*36
    float* khs  = qhs + 32 * 32;    // 64*36              }
    float* Ls   = khs + 64 * 36;    // 32*64
    float* W1qs = Ls + 32 * 64;     // 4*32
    float* b1s  = W1qs + 128;       // 32
    float* W2s  = b1s + 32;         // 32
    float* lngs = W2s + 32;         // 128
    float* lnbs = lngs + 128;       // 128
    float* Wfs  = lnbs + 128;       // 8
    float* msk  = Wfs + 8;          // 64
    float* alphaT = qhs;            // 64*36

    int bt = blockIdx.x;
    int ih = blockIdx.y;            // i-half: rows ih*32..+31
    int b = bt / 96, t = bt - b * 96;
    int tid = threadIdx.x;
    int warp = tid >> 5, lane = tid & 31;

    // ---- Phase A: loads ----
    const float* xbase = x + (size_t)((b * 64 + ih * 32) * 96 + t) * 128;
    const float* s1 = g_S1 + (size_t)(bt * 64) * SCOLS;
    #pragma unroll
    for (int it = 0; it < 4; it++) {
        int idx = tid + it * 256;
        int i = idx >> 5, c4 = (idx & 31) * 4;
        *(float4*)(Zs + i * 132 + c4) = *(const float4*)(xbase + (size_t)i * 96 * 128 + c4);
    }
    {
        int i = tid >> 3, c4 = (tid & 7) * 4;   // 32 rows x 32 cols
        *(float4*)(qhs + i * 32 + c4) = *(const float4*)(s1 + (size_t)(ih * 32 + i) * SCOLS + 256 + c4);
    }
    #pragma unroll
    for (int it = 0; it < 2; it++) {
        int idx = tid + it * 256;
        int i = idx >> 3, c4 = (idx & 7) * 4;
        *(float4*)(khs + i * 36 + c4) = *(const float4*)(s1 + (size_t)i * SCOLS + 288 + c4);
    }
    if (tid < 128) {
        int q = tid >> 5, tt = tid & 31;
        W1qs[q * 32 + tt] = W1[(256 + q) * 32 + tt];
        lngs[tid] = lng[tid];
        lnbs[tid] = lnb[tid];
    }
    if (tid < 32) { b1s[tid] = b1[tid]; W2s[tid] = W2[tid]; }
    if (tid < 5) Wfs[tid] = Wfuse[tid];
    if (tid < 64) msk[tid] = (float)maskp[b * 64 + tid];
    __syncthreads();
    // fold b1 into qhs (1024 floats)
    #pragma unroll
    for (int it = 0; it < 4; it++) {
        int idx = tid + it * 256;
        qhs[idx] += b1s[idx & 31];
    }
    __syncthreads();

    float pwv = pw[0], prwv = prw[0], b2v = b2[0];

    // ---- Phase B: logits, 2x4 tile per thread ----
    int ti = tid >> 4, tj = tid & 15;
    int i0l = ti * 2;               // local rows i0l, i0l+1
    int j0 = tj * 4;
    const float* ebase = edge + (size_t)bt * 4096 * 4 + (size_t)ih * 32 * 64 * 4;
    const float* pbase = prior + (size_t)bt * 4096 * 5 + (size_t)ih * 32 * 64 * 5;

    // edge features for the 2x4 tile
    float4 ef[2][4];
    #pragma unroll
    for (int u = 0; u < 2; u++)
        #pragma unroll
        for (int j = 0; j < 4; j++)
            ef[u][j] = *(const float4*)(ebase + (size_t)((i0l + u) * 64 + j0 + j) * 4);

    float p[2][4];
    #pragma unroll
    for (int u = 0; u < 2; u++)
        #pragma unroll
        for (int j = 0; j < 4; j++) p[u][j] = 0.f;

    #pragma unroll
    for (int tt = 0; tt < 32; tt += 4) {
        float4 w2v = *(float4*)(W2s + tt);
        float4 wq0 = *(float4*)(W1qs + 0 * 32 + tt);
        float4 wq1 = *(float4*)(W1qs + 1 * 32 + tt);
        float4 wq2 = *(float4*)(W1qs + 2 * 32 + tt);
        float4 wq3 = *(float4*)(W1qs + 3 * 32 + tt);
        u64 w0a = pk2(wq0.x, wq0.y), w0b = pk2(wq0.z, wq0.w);
        u64 w1a = pk2(wq1.x, wq1.y), w1b = pk2(wq1.z, wq1.w);
        u64 w2a = pk2(wq2.x, wq2.y), w2b = pk2(wq2.z, wq2.w);
        u64 w3a = pk2(wq3.x, wq3.y), w3b = pk2(wq3.z, wq3.w);
        u64 qa[2], qb_[2];
        #pragma unroll
        for (int u = 0; u < 2; u++) {
            float4 q4 = *(float4*)(qhs + (i0l + u) * 32 + tt);
            qa[u] = pk2(q4.x, q4.y); qb_[u] = pk2(q4.z, q4.w);
        }
        #pragma unroll
        for (int j = 0; j < 4; j++) {
            float4 kh = *(float4*)(khs + (j0 + j) * 36 + tt);
            u64 k01 = pk2(kh.x, kh.y), k23 = pk2(kh.z, kh.w);
            #pragma unroll
            for (int u = 0; u < 2; u++) {
                u64 ex = pk2(ef[u][j].x, ef[u][j].x);
                u64 ey = pk2(ef[u][j].y, ef[u][j].y);
                u64 ez = pk2(ef[u][j].z, ef[u][j].z);
                u64 ew = pk2(ef[u][j].w, ef[u][j].w);
                u64 h01 = add2_(qa[u], k01);
                h01 = fma2_(ex, w0a, h01);
                h01 = fma2_(ey, w1a, h01);
                h01 = fma2_(ez, w2a, h01);
                h01 = fma2_(ew, w3a, h01);
                float2 hf = up2(h01);
                float pj = p[u][j];
                pj = fmaf(fmaxf(hf.x, 0.f), w2v.x, pj);
                pj = fmaf(fmaxf(hf.y, 0.f), w2v.y, pj);
                u64 h23 = add2_(qb_[u], k23);
                h23 = fma2_(ex, w0b, h23);
                h23 = fma2_(ey, w1b, h23);
                h23 = fma2_(ez, w2b, h23);
                h23 = fma2_(ew, w3b, h23);
                hf = up2(h23);
                pj = fmaf(fmaxf(hf.x, 0.f), w2v.z, pj);
                pj = fmaf(fmaxf(hf.y, 0.f), w2v.w, pj);
                p[u][j] = pj;
            }
        }
    }

    const float* cbase = g_C + (size_t)bt * 4096;
    #pragma unroll
    for (int u = 0; u < 2; u++) {
        int il = i0l + u;
        int ig = ih * 32 + il;
        float pr[20];
        const float* ap0 = pbase + (size_t)(il * 64 + j0) * 5;
        *(float4*)(pr + 0)  = *(const float4*)(ap0 + 0);
        *(float4*)(pr + 4)  = *(const float4*)(ap0 + 4);
        *(float4*)(pr + 8)  = *(const float4*)(ap0 + 8);
        *(float4*)(pr + 12) = *(const float4*)(ap0 + 12);
        *(float4*)(pr + 16) = *(const float4*)(ap0 + 16);
        float4 cnt = *(const float4*)(cbase + (size_t)ig * 64 + j0);
        float cv[4] = {cnt.x, cnt.y, cnt.z, cnt.w};
        float Lv[4];
        #pragma unroll
        for (int v = 0; v < 4; v++) {
            float Ap = pr[v*5+0]*Wfs[0] + pr[v*5+1]*Wfs[1] + pr[v*5+2]*Wfs[2]
                     + pr[v*5+3]*Wfs[3] + pr[v*5+4]*Wfs[4];
            Ap = fmaxf(Ap, 0.f);
            float L = cv[v] + pwv * (p[u][v] + b2v) + prwv * __logf(Ap + 1e-6f);
            if (msk[ig] != 0.f || msk[j0 + v] != 0.f) L = -1e9f;
            Lv[v] = L;
        }
        *(float4*)(Ls + il * 64 + j0) = make_float4(Lv[0], Lv[1], Lv[2], Lv[3]);
    }
    __syncthreads();

    // ---- Phase C: softmax (32 local rows), transposed alpha over qhs/khs ----
    #pragma unroll 1
    for (int rr = 0; rr < 4; rr++) {
        int r = warp + rr * 8;
        float v0 = Ls[r * 64 + lane], v1 = Ls[r * 64 + lane + 32];
        float m = fmaxf(v0, v1);
        #pragma unroll
        for (int o = 16; o; o >>= 1) m = fmaxf(m, __shfl_xor_sync(0xffffffffu, m, o));
        float e0 = __expf(v0 - m), e1 = __expf(v1 - m);
        float s = e0 + e1;
        #pragma unroll
        for (int o = 16; o; o >>= 1) s += __shfl_xor_sync(0xffffffffu, s, o);
        float inv = 1.f / s;
        alphaT[lane * 36 + r] = e0 * inv;
        alphaT[(lane + 32) * 36 + r] = e1 * inv;
    }
    __syncthreads();

    // ---- Phase D: h = Z + alpha @ Vt (V streamed from L2), store into Zs ----
    int di = tid & 127, grp = tid >> 7;
    const float* vrow = g_S1 + (size_t)(bt * 64) * SCOLS + 128 + di;
    {
        int r0 = grp * 16;
        u64 acc2[8];
        #pragma unroll
        for (int q = 0; q < 8; q++)
            acc2[q] = pk2(Zs[(r0 + 2*q) * 132 + di], Zs[(r0 + 2*q + 1) * 132 + di]);
        #pragma unroll 4
        for (int jj = 0; jj < 64; jj++) {
            float vv = __ldg(vrow + (size_t)jj * SCOLS);
            u64 vv2 = pk2(vv, vv);
            float4 a0 = *(float4*)(alphaT + jj * 36 + r0);
            float4 a1 = *(float4*)(alphaT + jj * 36 + r0 + 4);
            float4 a2 = *(float4*)(alphaT + jj * 36 + r0 + 8);
            float4 a3 = *(float4*)(alphaT + jj * 36 + r0 + 12);
            acc2[0] = fma2_(pk2(a0.x, a0.y), vv2, acc2[0]);
            acc2[1] = fma2_(pk2(a0.z, a0.w), vv2, acc2[1]);
            acc2[2] = fma2_(pk2(a1.x, a1.y), vv2, acc2[2]);
            acc2[3] = fma2_(pk2(a1.z, a1.w), vv2, acc2[3]);
            acc2[4] = fma2_(pk2(a2.x, a2.y), vv2, acc2[4]);
            acc2[5] = fma2_(pk2(a2.z, a2.w), vv2, acc2[5]);
            acc2[6] = fma2_(pk2(a3.x, a3.y), vv2, acc2[6]);
            acc2[7] = fma2_(pk2(a3.z, a3.w), vv2, acc2[7]);
        }
        #pragma unroll
        for (int q = 0; q < 8; q++) {
            float2 f = up2(acc2[q]);
            Zs[(r0 + 2*q) * 132 + di] = f.x;
            Zs[(r0 + 2*q + 1) * 132 + di] = f.y;
        }
    }
    __syncthreads();

    // ---- Phase E: LayerNorm + masked, transposed store ----
    float* outb = out + (size_t)((b * 64) * 96 + t) * 128;
    #pragma unroll 1
    for (int rr = 0; rr < 4; rr++) {
        int r = warp + rr * 8;          // local
        int rg = ih * 32 + r;           // global row
        float v[4];
        #pragma unroll
        for (int u = 0; u < 4; u++) v[u] = Zs[r * 132 + lane + 32 * u];
        float s = v[0] + v[1] + v[2] + v[3];
        #pragma unroll
        for (int o = 16; o; o >>= 1) s += __shfl_xor_sync(0xffffffffu, s, o);
        float mu = s * (1.f / 128.f);
        float q = 0.f;
        #pragma unroll
        for (int u = 0; u < 4; u++) { float d = v[u] - mu; q = fmaf(d, d, q); }
        #pragma unroll
        for (int o = 16; o; o >>= 1) q += __shfl_xor_sync(0xffffffffu, q, o);
        float inv = rsqrtf(q * (1.f / 128.f) + 1e-5f);
        float keep = (msk[rg] != 0.f) ? 0.f : 1.f;
        float* op = outb + (size_t)rg * 96 * 128;
        #pragma unroll
        for (int u = 0; u < 4; u++) {
            int d = lane + 32 * u;
            op[d] = ((v[u] - mu) * inv * lngs[d] + lnbs[d]) * keep;
        }
    }
}

extern "C" void kernel_launch(void* const* d_in, const int* in_sizes, int n_in,
                              void* d_out, int out_size) {
    const float* x     = (const float*)d_in[0];
    const float* edge  = (const float*)d_in[1];
    const float* prior = (const float*)d_in[2];
    const unsigned char* maskp = (const unsigned char*)d_in[3];
    const float* Wq    = (const float*)d_in[4];
    const float* Wk    = (const float*)d_in[5];
    const float* Wv    = (const float*)d_in[6];
    const float* W1    = (const float*)d_in[7];
    const float* b1    = (const float*)d_in[8];
    const float* W2    = (const float*)d_in[9];
    const float* b2    = (const float*)d_in[10];
    const float* Wfuse = (const float*)d_in[11];
    const float* Wth   = (const float*)d_in[12];
    const float* lng   = (const float*)d_in[13];
    const float* lnb   = (const float*)d_in[14];
    const float* pw    = (const float*)d_in[15];
    const float* prw   = (const float*)d_in[16];
    float* out = (float*)d_out;

    static int inited = 0;
    if (!inited) {
        cudaFuncSetAttribute(k1_gemm, cudaFuncAttributeMaxDynamicSharedMemorySize, K1_SMEM);
        cudaFuncSetAttribute(k1b_content, cudaFuncAttributeMaxDynamicSharedMemorySize, K1B_SMEM);
        cudaFuncSetAttribute(k2_attn, cudaFuncAttributeMaxDynamicSharedMemorySize, K2_SMEM);
        inited = 1;
    }

    k0_fuse<<<dim3(10, 4), 256>>>(Wq, Wk, Wv, W1, Wth);
    k1_gemm<<<dim3(96, 3), 256, K1_SMEM>>>(x);
    k1b_content<<<192, 256, K1B_SMEM>>>(x);
    k2_attn<<<dim3(192, 2), 256, K2_SMEM>>>(x, edge, prior, maskp, W1, b1, W2, b2,
                                            Wfuse, lng, lnb, pw, prw, out);
}